// round 1
// baseline (speedup 1.0000x reference)
#include <cuda_runtime.h>
#include <math.h>

// Problem constants
#define Bb   4
#define Cc   128
#define Tt   16
#define Hh   56
#define Ww   56
#define THW  50176      // Tt*Hh*Ww
#define TOK  200704     // Bb*THW
#define NWIN 1024       // Bb * (Tt/4) * (Hh/7) * (Ww/7) = 4*4*8*8
#define NTOK 196        // 4*7*7
#define HID  512

// ---------------- scratch (device globals; no allocations) ----------------
__device__ float g_win[(size_t)NWIN * NTOK * Cc];   // BN'd windows, later attn output
__device__ float g_xtok[(size_t)TOK * Cc];          // raw x token-major, later LN output f
__device__ float g_big[(size_t)TOK * HID];          // qkv (uses 77M), later fc1 hidden (103M)
__device__ float g_y[(size_t)TOK * Cc];             // x + attn residual (token-major)

// ============================================================
// Kernel 1: BN + window partition + token-major raw copy
// grid (Tt*Hh=896, Cc/32=4, Bb=4), block 256
// ============================================================
__global__ __launch_bounds__(256) void bn_window_kernel(
    const float* __restrict__ x, const float* __restrict__ gamma,
    const float* __restrict__ beta, const float* __restrict__ mean,
    const float* __restrict__ var, float* __restrict__ win,
    float* __restrict__ xtok)
{
    __shared__ float rawS[32][57];
    __shared__ float bnS[32][57];
    const int gx = blockIdx.x;
    const int t = gx / 56, h = gx % 56;
    const int c0 = blockIdx.y * 32;
    const int b = blockIdx.z;
    const int tid = threadIdx.x;

#pragma unroll
    for (int it = 0; it < 7; it++) {
        int idx = tid + it * 256;           // 0..1791 over (32c x 56w)
        int i = idx / 56, j = idx % 56;
        int c = c0 + i;
        size_t off = ((((size_t)b * Cc + c) * Tt + t) * Hh + h) * Ww + j;
        float v = x[off];
        rawS[i][j] = v;
        float inv = rsqrtf(var[c] + 1e-5f);
        bnS[i][j] = (v - mean[c]) * (inv * gamma[c]) + beta[c];
    }
    __syncthreads();

    const int tblk = t >> 2, wt = t & 3;
    const int hblk = h / 7, wh = h % 7;
#pragma unroll
    for (int it = 0; it < 7; it++) {
        int idx = tid + it * 256;
        int i = idx & 31;       // channel within tile (lane -> contiguous writes)
        int j = idx >> 5;       // w position 0..55
        int wblk = j / 7, ww2 = j % 7;
        int widx = ((b * 4 + tblk) * 8 + hblk) * 8 + wblk;
        int n = (wt * 7 + wh) * 7 + ww2;
        win[((size_t)widx * NTOK + n) * Cc + c0 + i] = bnS[i][j];
        size_t tok = (size_t)b * THW + ((size_t)t * Hh + h) * Ww + j;
        xtok[tok * Cc + c0 + i] = rawS[i][j];
    }
}

// ============================================================
// Generic fp32 GEMM: out(M x N) = A(M x K) @ W(K x N) + bias, fused epilogues
// tile 64x64, 256 threads, 4x4 micro-tile. M=200704 (div by 64), N,K div by 32/64.
// EPI 0: plain   1: proj(+window-reverse residual -> g_y)
// EPI 2: GELU    3: fc2(+residual from g_y, transposed store to B,C,THW)
// ============================================================
__device__ __forceinline__ float gelu_exact(float v) {
    return 0.5f * v * (1.0f + erff(v * 0.7071067811865475f));
}

template<int NDIM, int KDIM, int EPI>
__global__ __launch_bounds__(256) void gemm_kernel(
    const float* __restrict__ A, const float* __restrict__ Wm,
    const float* __restrict__ bias, float* __restrict__ out,
    const float* __restrict__ res)
{
    __shared__ float As[64][33];
    __shared__ float Bs[32][68];
    const int cb = blockIdx.x * 64;
    const int rb = blockIdx.y * 64;
    const int tid = threadIdx.x;
    const int tx = tid & 15, ty = tid >> 4;
    float acc[4][4] = {};

    const int kkA = tid & 31, r0A = tid >> 5;
    const int ccB = (tid & 15) * 4, kk0B = tid >> 4;

    for (int k0 = 0; k0 < KDIM; k0 += 32) {
#pragma unroll
        for (int p = 0; p < 8; p++) {
            int r = r0A + p * 8;
            As[r][kkA] = A[(size_t)(rb + r) * KDIM + k0 + kkA];
        }
#pragma unroll
        for (int p = 0; p < 2; p++) {
            int kk = kk0B + p * 16;
            *(float4*)&Bs[kk][ccB] =
                *(const float4*)&Wm[(size_t)(k0 + kk) * NDIM + cb + ccB];
        }
        __syncthreads();
#pragma unroll
        for (int kk = 0; kk < 32; kk++) {
            float a0 = As[ty * 4 + 0][kk];
            float a1 = As[ty * 4 + 1][kk];
            float a2 = As[ty * 4 + 2][kk];
            float a3 = As[ty * 4 + 3][kk];
            float4 b4 = *(const float4*)&Bs[kk][tx * 4];
            acc[0][0] += a0 * b4.x; acc[0][1] += a0 * b4.y; acc[0][2] += a0 * b4.z; acc[0][3] += a0 * b4.w;
            acc[1][0] += a1 * b4.x; acc[1][1] += a1 * b4.y; acc[1][2] += a1 * b4.z; acc[1][3] += a1 * b4.w;
            acc[2][0] += a2 * b4.x; acc[2][1] += a2 * b4.y; acc[2][2] += a2 * b4.z; acc[2][3] += a2 * b4.w;
            acc[3][0] += a3 * b4.x; acc[3][1] += a3 * b4.y; acc[3][2] += a3 * b4.z; acc[3][3] += a3 * b4.w;
        }
        __syncthreads();
    }

    float4 bias4 = *(const float4*)&bias[cb + tx * 4];

    if constexpr (EPI == 0) {
#pragma unroll
        for (int i = 0; i < 4; i++) {
            float4 o;
            o.x = acc[i][0] + bias4.x; o.y = acc[i][1] + bias4.y;
            o.z = acc[i][2] + bias4.z; o.w = acc[i][3] + bias4.w;
            *(float4*)&out[(size_t)(rb + ty * 4 + i) * NDIM + cb + tx * 4] = o;
        }
    } else if constexpr (EPI == 1) {
        // rows are window-order; scatter to raw-token order with residual
#pragma unroll
        for (int i = 0; i < 4; i++) {
            unsigned r = rb + ty * 4 + i;
            unsigned widx = r / 196u, nl = r - widx * 196u;
            unsigned wblk = widx & 7u, hblk = (widx >> 3) & 7u;
            unsigned tblk = (widx >> 6) & 3u, bbx = widx >> 8;
            unsigned wt = nl / 49u, rem = nl - wt * 49u;
            unsigned wh = rem / 7u, w2 = rem - wh * 7u;
            unsigned th = tblk * 4 + wt, hp = hblk * 7 + wh, wp = wblk * 7 + w2;
            size_t tok = (size_t)bbx * THW + ((size_t)th * Hh + hp) * Ww + wp;
            float4 xres = *(const float4*)&res[tok * Cc + cb + tx * 4];
            float4 o;
            o.x = acc[i][0] + bias4.x + xres.x;
            o.y = acc[i][1] + bias4.y + xres.y;
            o.z = acc[i][2] + bias4.z + xres.z;
            o.w = acc[i][3] + bias4.w + xres.w;
            *(float4*)&out[tok * Cc + cb + tx * 4] = o;
        }
    } else if constexpr (EPI == 2) {
#pragma unroll
        for (int i = 0; i < 4; i++) {
            float4 o;
            o.x = gelu_exact(acc[i][0] + bias4.x);
            o.y = gelu_exact(acc[i][1] + bias4.y);
            o.z = gelu_exact(acc[i][2] + bias4.z);
            o.w = gelu_exact(acc[i][3] + bias4.w);
            *(float4*)&out[(size_t)(rb + ty * 4 + i) * NDIM + cb + tx * 4] = o;
        }
    } else {  // EPI == 3: residual + transpose to (B, C, THW)
#pragma unroll
        for (int i = 0; i < 4; i++) {
            unsigned r = rb + ty * 4 + i;
            unsigned bbx = r / (unsigned)THW;
            unsigned thw = r - bbx * (unsigned)THW;
            float4 yres = *(const float4*)&res[(size_t)r * Cc + cb + tx * 4];
            float v0 = acc[i][0] + bias4.x + yres.x;
            float v1 = acc[i][1] + bias4.y + yres.y;
            float v2 = acc[i][2] + bias4.z + yres.z;
            float v3 = acc[i][3] + bias4.w + yres.w;
            size_t ob = ((size_t)bbx * Cc + cb + tx * 4) * THW + thw;
            out[ob + 0 * (size_t)THW] = v0;
            out[ob + 1 * (size_t)THW] = v1;
            out[ob + 2 * (size_t)THW] = v2;
            out[ob + 3 * (size_t)THW] = v3;
        }
    }
}

// ============================================================
// Attention: one CTA per (window, head). K,V in smem (50 KB dynamic),
// one query row per thread, two-pass softmax.
// ============================================================
__global__ __launch_bounds__(224) void attn_kernel(
    const float* __restrict__ qkv, float* __restrict__ outp)
{
    extern __shared__ float sm[];
    float* ks = sm;
    float* vs = sm + 6272;
    const int widx = blockIdx.x, hh = blockIdx.y;
    const size_t base = (size_t)widx * NTOK * 384 + hh * 32;

    for (int idx = threadIdx.x; idx < 6272; idx += 224) {
        int n = idx >> 5, d = idx & 31;
        size_t rowoff = base + (size_t)n * 384;
        ks[idx] = qkv[rowoff + 128 + d];
        vs[idx] = qkv[rowoff + 256 + d];
    }
    __syncthreads();

    const int row = threadIdx.x;
    if (row >= NTOK) return;

    const float sc = 0.17677669529663688f;  // 1/sqrt(32)
    float q[32];
    const float* qp = &qkv[base + (size_t)row * 384];
#pragma unroll
    for (int d4 = 0; d4 < 8; d4++) {
        float4 t4 = *(const float4*)(qp + 4 * d4);
        q[4 * d4 + 0] = t4.x * sc; q[4 * d4 + 1] = t4.y * sc;
        q[4 * d4 + 2] = t4.z * sc; q[4 * d4 + 3] = t4.w * sc;
    }

    float m = -1e30f;
    for (int j = 0; j < NTOK; j++) {
        const float* kp = ks + j * 32;
        float dot = 0.f;
#pragma unroll
        for (int d4 = 0; d4 < 8; d4++) {
            float4 k4 = *(const float4*)(kp + 4 * d4);
            dot += q[4 * d4 + 0] * k4.x + q[4 * d4 + 1] * k4.y
                 + q[4 * d4 + 2] * k4.z + q[4 * d4 + 3] * k4.w;
        }
        m = fmaxf(m, dot);
    }

    float s = 0.f;
    float acc[32];
#pragma unroll
    for (int d = 0; d < 32; d++) acc[d] = 0.f;

    for (int j = 0; j < NTOK; j++) {
        const float* kp = ks + j * 32;
        float dot = 0.f;
#pragma unroll
        for (int d4 = 0; d4 < 8; d4++) {
            float4 k4 = *(const float4*)(kp + 4 * d4);
            dot += q[4 * d4 + 0] * k4.x + q[4 * d4 + 1] * k4.y
                 + q[4 * d4 + 2] * k4.z + q[4 * d4 + 3] * k4.w;
        }
        float e = __expf(dot - m);
        s += e;
        const float* vp = vs + j * 32;
#pragma unroll
        for (int d4 = 0; d4 < 8; d4++) {
            float4 v4 = *(const float4*)(vp + 4 * d4);
            acc[4 * d4 + 0] += e * v4.x; acc[4 * d4 + 1] += e * v4.y;
            acc[4 * d4 + 2] += e * v4.z; acc[4 * d4 + 3] += e * v4.w;
        }
    }

    float invs = 1.f / s;
    float* op = &outp[((size_t)widx * NTOK + row) * Cc + hh * 32];
#pragma unroll
    for (int d4 = 0; d4 < 8; d4++) {
        float4 o;
        o.x = acc[4 * d4 + 0] * invs; o.y = acc[4 * d4 + 1] * invs;
        o.z = acc[4 * d4 + 2] * invs; o.w = acc[4 * d4 + 3] * invs;
        *(float4*)(op + 4 * d4) = o;
    }
}

// ============================================================
// LayerNorm: one warp per token (C=128 -> 4 floats per lane)
// ============================================================
__global__ __launch_bounds__(256) void ln_kernel(
    const float* __restrict__ y, const float* __restrict__ g,
    const float* __restrict__ bt, float* __restrict__ f)
{
    const int warp = threadIdx.x >> 5, lane = threadIdx.x & 31;
    const size_t tok = (size_t)blockIdx.x * 8 + warp;
    const float4 v = *(const float4*)&y[tok * Cc + lane * 4];
    float sum = v.x + v.y + v.z + v.w;
#pragma unroll
    for (int o = 16; o > 0; o >>= 1) sum += __shfl_xor_sync(0xffffffffu, sum, o);
    float mu = sum * (1.f / 128.f);
    float dx = v.x - mu, dy = v.y - mu, dz = v.z - mu, dw = v.w - mu;
    float sq = dx * dx + dy * dy + dz * dz + dw * dw;
#pragma unroll
    for (int o = 16; o > 0; o >>= 1) sq += __shfl_xor_sync(0xffffffffu, sq, o);
    float inv = rsqrtf(sq * (1.f / 128.f) + 1e-5f);
    float4 gg = *(const float4*)&g[lane * 4];
    float4 bb = *(const float4*)&bt[lane * 4];
    float4 o;
    o.x = dx * inv * gg.x + bb.x; o.y = dy * inv * gg.y + bb.y;
    o.z = dz * inv * gg.z + bb.z; o.w = dw * inv * gg.w + bb.w;
    *(float4*)&f[tok * Cc + lane * 4] = o;
}

// ============================================================
// Launch
// ============================================================
extern "C" void kernel_launch(void* const* d_in, const int* in_sizes, int n_in,
                              void* d_out, int out_size)
{
    const float* x      = (const float*)d_in[0];
    const float* bn_g   = (const float*)d_in[1];
    const float* bn_b   = (const float*)d_in[2];
    const float* bn_m   = (const float*)d_in[3];
    const float* bn_v   = (const float*)d_in[4];
    const float* qkv_w  = (const float*)d_in[5];
    const float* qkv_b  = (const float*)d_in[6];
    const float* proj_w = (const float*)d_in[7];
    const float* proj_b = (const float*)d_in[8];
    const float* ln_g   = (const float*)d_in[9];
    const float* ln_b   = (const float*)d_in[10];
    const float* fc1_w  = (const float*)d_in[11];
    const float* fc1_b  = (const float*)d_in[12];
    const float* fc2_w  = (const float*)d_in[13];
    const float* fc2_b  = (const float*)d_in[14];
    float* out = (float*)d_out;

    float *p_win, *p_xtok, *p_big, *p_y;
    cudaGetSymbolAddress((void**)&p_win, g_win);
    cudaGetSymbolAddress((void**)&p_xtok, g_xtok);
    cudaGetSymbolAddress((void**)&p_big, g_big);
    cudaGetSymbolAddress((void**)&p_y, g_y);

    cudaFuncSetAttribute(attn_kernel, cudaFuncAttributeMaxDynamicSharedMemorySize, 50176);

    // 1. BN + window partition (g_win) + raw token-major copy (g_xtok)
    bn_window_kernel<<<dim3(896, 4, 4), 256>>>(x, bn_g, bn_b, bn_m, bn_v, p_win, p_xtok);

    // 2. QKV GEMM: (200704 x 128) @ (128 x 384) -> g_big
    gemm_kernel<384, 128, 0><<<dim3(6, 3136), 256>>>(p_win, qkv_w, qkv_b, p_big, nullptr);

    // 3. Windowed attention -> g_win (window-order, per-head concat)
    attn_kernel<<<dim3(1024, 4), 224, 50176>>>(p_big, p_win);

    // 4. Proj GEMM + window-reverse + residual -> g_y (token-major)
    gemm_kernel<128, 128, 1><<<dim3(2, 3136), 256>>>(p_win, proj_w, proj_b, p_y, p_xtok);

    // 5. LayerNorm -> g_xtok (reused as f)
    ln_kernel<<<25088, 256>>>(p_y, ln_g, ln_b, p_xtok);

    // 6. fc1 GEMM + exact GELU -> g_big (reused as hidden)
    gemm_kernel<512, 128, 2><<<dim3(8, 3136), 256>>>(p_xtok, fc1_w, fc1_b, p_big, nullptr);

    // 7. fc2 GEMM + residual + transpose store -> d_out (B,C,T,H,W)
    gemm_kernel<128, 512, 3><<<dim3(2, 3136), 256>>>(p_big, fc2_w, fc2_b, out, p_y);
}

// round 4
// speedup vs baseline: 2.2799x; 2.2799x over previous
#include <cuda_runtime.h>
#include <cuda_bf16.h>
#include <math.h>
#include <stdint.h>

// ---------------- problem constants ----------------
#define Bb   4
#define Cc   128
#define Tt   16
#define Hh   56
#define Ww   56
#define THW  50176      // Tt*Hh*Ww
#define TOK  200704     // Bb*THW
#define NTOK 196        // 4*7*7
#define HID  512

// ---------------- scratch (device globals) ----------------
__device__ __nv_bfloat16 g_win [(size_t)TOK * Cc];    // BN'd windows (bf16, window order)
__device__ __nv_bfloat16 g_qkv [(size_t)TOK * 384];   // qkv (bf16, window order)
__device__ __nv_bfloat16 g_attn[(size_t)TOK * Cc];    // attention out (bf16, window order)
__device__ __nv_bfloat16 g_f   [(size_t)TOK * Cc];    // LN out (bf16, token order)
__device__ __nv_bfloat16 g_hid [(size_t)TOK * HID];   // gelu(fc1) (bf16, token order)
__device__ float         g_xtok[(size_t)TOK * Cc];    // raw x (fp32, token order)
__device__ float         g_y   [(size_t)TOK * Cc];    // x + attn residual (fp32, token order)
// transposed bf16 weights [N][K]
__device__ __nv_bfloat16 g_wq[384 * 128];
__device__ __nv_bfloat16 g_wp[128 * 128];
__device__ __nv_bfloat16 g_w1[512 * 128];
__device__ __nv_bfloat16 g_w2[128 * 512];

// ---------------- helpers ----------------
__device__ __forceinline__ uint32_t smem_u32(const void* p) {
    uint32_t a;
    asm("{ .reg .u64 t; cvta.to.shared.u64 t, %1; cvt.u32.u64 %0, t; }" : "=r"(a) : "l"(p));
    return a;
}
__device__ __forceinline__ void ldsm4(uint32_t* r, uint32_t addr) {
    asm volatile("ldmatrix.sync.aligned.m8n8.x4.shared.b16 {%0,%1,%2,%3}, [%4];"
        : "=r"(r[0]), "=r"(r[1]), "=r"(r[2]), "=r"(r[3]) : "r"(addr));
}
__device__ __forceinline__ void mma_bf16(float* d, const uint32_t* a, uint32_t b0, uint32_t b1) {
    asm volatile(
        "mma.sync.aligned.m16n8k16.row.col.f32.bf16.bf16.f32 "
        "{%0,%1,%2,%3}, {%4,%5,%6,%7}, {%8,%9}, {%0,%1,%2,%3};"
        : "+f"(d[0]), "+f"(d[1]), "+f"(d[2]), "+f"(d[3])
        : "r"(a[0]), "r"(a[1]), "r"(a[2]), "r"(a[3]), "r"(b0), "r"(b1));
}
__device__ __forceinline__ float gelu_exact(float v) {
    return 0.5f * v * (1.0f + erff(v * 0.7071067811865475f));
}

// ============================================================
// Weight transpose + bf16 convert: W[K][N] -> Wt[N][K] bf16
// ============================================================
__global__ __launch_bounds__(256) void wprep_kernel(
    const float* __restrict__ qkv_w, const float* __restrict__ proj_w,
    const float* __restrict__ fc1_w, const float* __restrict__ fc2_w)
{
    int i = blockIdx.x * 256 + threadIdx.x;
    if (i < 49152) {                       // qkv: 384x128
        int n = i >> 7, k = i & 127;
        g_wq[i] = __float2bfloat16_rn(qkv_w[k * 384 + n]);
    } else if (i < 65536) {                // proj: 128x128
        int j = i - 49152; int n = j >> 7, k = j & 127;
        g_wp[j] = __float2bfloat16_rn(proj_w[k * 128 + n]);
    } else if (i < 131072) {               // fc1: 512x128
        int j = i - 65536; int n = j >> 7, k = j & 127;
        g_w1[j] = __float2bfloat16_rn(fc1_w[k * 512 + n]);
    } else if (i < 196608) {               // fc2: 128x512
        int j = i - 131072; int n = j >> 9, k = j & 511;
        g_w2[j] = __float2bfloat16_rn(fc2_w[k * 128 + n]);
    }
}

// ============================================================
// BN + window partition (bf16) + token-major raw copy (fp32)
// ============================================================
__global__ __launch_bounds__(256) void bn_window_kernel(
    const float* __restrict__ x, const float* __restrict__ gamma,
    const float* __restrict__ beta, const float* __restrict__ mean,
    const float* __restrict__ var, __nv_bfloat16* __restrict__ win,
    float* __restrict__ xtok)
{
    __shared__ float rawS[32][57];
    __shared__ float bnS[32][57];
    const int gx = blockIdx.x;
    const int t = gx / 56, h = gx % 56;
    const int c0 = blockIdx.y * 32;
    const int b = blockIdx.z;
    const int tid = threadIdx.x;

#pragma unroll
    for (int it = 0; it < 7; it++) {
        int idx = tid + it * 256;
        int i = idx / 56, j = idx % 56;
        int c = c0 + i;
        size_t off = ((((size_t)b * Cc + c) * Tt + t) * Hh + h) * Ww + j;
        float v = x[off];
        rawS[i][j] = v;
        float inv = rsqrtf(var[c] + 1e-5f);
        bnS[i][j] = (v - mean[c]) * (inv * gamma[c]) + beta[c];
    }
    __syncthreads();

    const int tblk = t >> 2, wt = t & 3;
    const int hblk = h / 7, wh = h % 7;
#pragma unroll
    for (int it = 0; it < 7; it++) {
        int idx = tid + it * 256;
        int i = idx & 31, j = idx >> 5;
        int wblk = j / 7, ww2 = j % 7;
        int widx = ((b * 4 + tblk) * 8 + hblk) * 8 + wblk;
        int n = (wt * 7 + wh) * 7 + ww2;
        win[((size_t)widx * NTOK + n) * Cc + c0 + i] = __float2bfloat16_rn(bnS[i][j]);
        size_t tok = (size_t)b * THW + ((size_t)t * Hh + h) * Ww + j;
        xtok[tok * Cc + c0 + i] = rawS[i][j];
    }
}

// ============================================================
// bf16 HMMA GEMM (mma.sync.m16n8k16), CTA tile 128x128, 8 warps (4Mx2N),
// warp tile 32x64, K-chunk 64 in smem, fp32 accumulate.
// A: [M][KTOT] bf16 row-major; Bm: [N][KTOT] bf16 row-major (pre-transposed).
// EPI 0: bf16 +bias (qkv)      1: fp32 +bias+res window->token scatter (proj)
// EPI 2: gelu->bf16 (fc1)      3: fp32 +bias+res, transpose store (B,C,THW) (fc2)
// ============================================================
template<int KTOT, int NOUT, int EPI>
__global__ __launch_bounds__(256) void mma_gemm(
    const __nv_bfloat16* __restrict__ A, const __nv_bfloat16* __restrict__ Bm,
    const float* __restrict__ bias, void* __restrict__ outv,
    const float* __restrict__ res)
{
    __shared__ __nv_bfloat16 As[128][72];
    __shared__ __nv_bfloat16 Bs[128][72];
    const int tid = threadIdx.x;
    const int nb = blockIdx.x * 128;
    const int rb = blockIdx.y * 128;
    const int lane = tid & 31, wid = tid >> 5;
    const int wm = wid >> 1, wn = wid & 1;     // warp grid 4(M) x 2(N)

    float acc[2][8][4];
#pragma unroll
    for (int mt = 0; mt < 2; mt++)
#pragma unroll
        for (int nt = 0; nt < 8; nt++)
#pragma unroll
            for (int j = 0; j < 4; j++) acc[mt][nt][j] = 0.f;

    // ldmatrix source coordinates (within warp)
    const int aRow = lane & 15, aKH = lane >> 4;              // A: 16 rows, k-half
    const int bRow = ((lane >> 4) << 3) + (lane & 7);         // B: n row within 16
    const int bKH = (lane >> 3) & 1;                          // B: k-half

    for (int k0 = 0; k0 < KTOT; k0 += 64) {
#pragma unroll
        for (int p = 0; p < 4; p++) {
            int idx = tid + p * 256;           // 1024 16B-chunks per tile
            int row = idx >> 3, cc = idx & 7;
            *(uint4*)&As[row][cc * 8] =
                *(const uint4*)(A + (size_t)(rb + row) * KTOT + k0 + cc * 8);
            *(uint4*)&Bs[row][cc * 8] =
                *(const uint4*)(Bm + (size_t)(nb + row) * KTOT + k0 + cc * 8);
        }
        __syncthreads();

#pragma unroll
        for (int ks = 0; ks < 4; ks++) {
            const int kk = ks * 16;
            uint32_t a[2][4], b[4][4];
#pragma unroll
            for (int mt = 0; mt < 2; mt++)
                ldsm4(a[mt], smem_u32(&As[wm * 32 + mt * 16 + aRow][kk + aKH * 8]));
#pragma unroll
            for (int np = 0; np < 4; np++)
                ldsm4(b[np], smem_u32(&Bs[wn * 64 + np * 16 + bRow][kk + bKH * 8]));
#pragma unroll
            for (int mt = 0; mt < 2; mt++)
#pragma unroll
                for (int nt = 0; nt < 8; nt++)
                    mma_bf16(acc[mt][nt], a[mt], b[nt >> 1][(nt & 1) * 2],
                             b[nt >> 1][(nt & 1) * 2 + 1]);
        }
        __syncthreads();
    }

    // ---------------- epilogue ----------------
    const int gid = lane >> 2, tig = lane & 3;
#pragma unroll
    for (int mt = 0; mt < 2; mt++) {
#pragma unroll
        for (int half = 0; half < 2; half++) {
            const int R = rb + wm * 32 + mt * 16 + half * 8 + gid;

            if constexpr (EPI == 0 || EPI == 2) {
                __nv_bfloat16* po = (__nv_bfloat16*)outv + (size_t)R * NOUT;
#pragma unroll
                for (int nt = 0; nt < 8; nt++) {
                    int c = nb + wn * 64 + nt * 8 + tig * 2;
                    float v0 = acc[mt][nt][half * 2]     + bias[c];
                    float v1 = acc[mt][nt][half * 2 + 1] + bias[c + 1];
                    if constexpr (EPI == 2) { v0 = gelu_exact(v0); v1 = gelu_exact(v1); }
                    *(__nv_bfloat162*)(po + c) = __floats2bfloat162_rn(v0, v1);
                }
            } else if constexpr (EPI == 1) {
                unsigned r = (unsigned)R;
                unsigned widx = r / 196u, nl = r - widx * 196u;
                unsigned wblk = widx & 7u, hblk = (widx >> 3) & 7u;
                unsigned tblk = (widx >> 6) & 3u, bbx = widx >> 8;
                unsigned wt = nl / 49u, rem = nl - wt * 49u;
                unsigned wh = rem / 7u, w2 = rem - wh * 7u;
                unsigned th = tblk * 4 + wt, hp = hblk * 7 + wh, wp = wblk * 7 + w2;
                size_t tok = (size_t)bbx * THW + ((size_t)th * Hh + hp) * Ww + wp;
                float* po = (float*)outv + tok * Cc;
                const float* pr = res + tok * Cc;
#pragma unroll
                for (int nt = 0; nt < 8; nt++) {
                    int c = wn * 64 + nt * 8 + tig * 2;
                    float2 xr = *(const float2*)(pr + c);
                    float2 o;
                    o.x = acc[mt][nt][half * 2]     + bias[c]     + xr.x;
                    o.y = acc[mt][nt][half * 2 + 1] + bias[c + 1] + xr.y;
                    *(float2*)(po + c) = o;
                }
            } else {  // EPI == 3
                unsigned bq = (unsigned)R / (unsigned)THW;
                unsigned thw = (unsigned)R - bq * (unsigned)THW;
                const float* pr = res + (size_t)R * Cc;
                float* po = (float*)outv;
#pragma unroll
                for (int nt = 0; nt < 8; nt++) {
                    int c = wn * 64 + nt * 8 + tig * 2;
                    float2 xr = *(const float2*)(pr + c);
                    po[(size_t)(bq * Cc + c) * THW + thw] =
                        acc[mt][nt][half * 2] + bias[c] + xr.x;
                    po[(size_t)(bq * Cc + c + 1) * THW + thw] =
                        acc[mt][nt][half * 2 + 1] + bias[c + 1] + xr.y;
                }
            }
        }
    }
}

// ============================================================
// Attention: one CTA per (window, head). K,V fp32 in smem (50 KB),
// one query row per thread, single-pass softmax (logits bounded ~0.3).
// ============================================================
__global__ __launch_bounds__(224) void attn_kernel(
    const __nv_bfloat16* __restrict__ qkv, __nv_bfloat16* __restrict__ outp)
{
    extern __shared__ float smf[];
    float* ks = smf;
    float* vs = smf + 6272;
    const int widx = blockIdx.x, hh = blockIdx.y;
    const size_t base = (size_t)widx * NTOK * 384 + hh * 32;

    for (int idx = threadIdx.x; idx < 6272; idx += 224) {
        int n = idx >> 5, d = idx & 31;
        size_t rowoff = base + (size_t)n * 384;
        ks[idx] = __bfloat162float(qkv[rowoff + 128 + d]);
        vs[idx] = __bfloat162float(qkv[rowoff + 256 + d]);
    }
    __syncthreads();

    const int row = threadIdx.x;
    if (row >= NTOK) return;

    const float sc = 0.17677669529663688f;  // 1/sqrt(32)
    float q[32];
    const __nv_bfloat16* qp = qkv + base + (size_t)row * 384;
#pragma unroll
    for (int d = 0; d < 32; d++) q[d] = __bfloat162float(qp[d]) * sc;

    float s = 0.f;
    float acc[32];
#pragma unroll
    for (int d = 0; d < 32; d++) acc[d] = 0.f;

    for (int j = 0; j < NTOK; j++) {
        const float* kp = ks + j * 32;
        float dot = 0.f;
#pragma unroll
        for (int d4 = 0; d4 < 8; d4++) {
            float4 k4 = *(const float4*)(kp + 4 * d4);
            dot += q[4 * d4 + 0] * k4.x + q[4 * d4 + 1] * k4.y
                 + q[4 * d4 + 2] * k4.z + q[4 * d4 + 3] * k4.w;
        }
        float e = __expf(dot);
        s += e;
        const float* vp = vs + j * 32;
#pragma unroll
        for (int d4 = 0; d4 < 8; d4++) {
            float4 v4 = *(const float4*)(vp + 4 * d4);
            acc[4 * d4 + 0] += e * v4.x; acc[4 * d4 + 1] += e * v4.y;
            acc[4 * d4 + 2] += e * v4.z; acc[4 * d4 + 3] += e * v4.w;
        }
    }

    float invs = 1.f / s;
    __nv_bfloat16* op = outp + ((size_t)widx * NTOK + row) * Cc + hh * 32;
#pragma unroll
    for (int d = 0; d < 32; d += 2) {
        *(__nv_bfloat162*)(op + d) =
            __floats2bfloat162_rn(acc[d] * invs, acc[d + 1] * invs);
    }
}

// ============================================================
// LayerNorm: one warp per token, fp32 in -> bf16 out
// ============================================================
__global__ __launch_bounds__(256) void ln_kernel(
    const float* __restrict__ y, const float* __restrict__ g,
    const float* __restrict__ bt, __nv_bfloat16* __restrict__ f)
{
    const int warp = threadIdx.x >> 5, lane = threadIdx.x & 31;
    const size_t tok = (size_t)blockIdx.x * 8 + warp;
    const float4 v = *(const float4*)&y[tok * Cc + lane * 4];
    float sum = v.x + v.y + v.z + v.w;
#pragma unroll
    for (int o = 16; o > 0; o >>= 1) sum += __shfl_xor_sync(0xffffffffu, sum, o);
    float mu = sum * (1.f / 128.f);
    float dx = v.x - mu, dy = v.y - mu, dz = v.z - mu, dw = v.w - mu;
    float sq = dx * dx + dy * dy + dz * dz + dw * dw;
#pragma unroll
    for (int o = 16; o > 0; o >>= 1) sq += __shfl_xor_sync(0xffffffffu, sq, o);
    float inv = rsqrtf(sq * (1.f / 128.f) + 1e-5f);
    float4 gg = *(const float4*)&g[lane * 4];
    float4 bb = *(const float4*)&bt[lane * 4];
    __nv_bfloat16* po = f + tok * Cc + lane * 4;
    *(__nv_bfloat162*)(po)     = __floats2bfloat162_rn(dx * inv * gg.x + bb.x, dy * inv * gg.y + bb.y);
    *(__nv_bfloat162*)(po + 2) = __floats2bfloat162_rn(dz * inv * gg.z + bb.z, dw * inv * gg.w + bb.w);
}

// ============================================================
// Launch
// ============================================================
extern "C" void kernel_launch(void* const* d_in, const int* in_sizes, int n_in,
                              void* d_out, int out_size)
{
    const float* x      = (const float*)d_in[0];
    const float* bn_g   = (const float*)d_in[1];
    const float* bn_b   = (const float*)d_in[2];
    const float* bn_m   = (const float*)d_in[3];
    const float* bn_v   = (const float*)d_in[4];
    const float* qkv_w  = (const float*)d_in[5];
    const float* qkv_b  = (const float*)d_in[6];
    const float* proj_w = (const float*)d_in[7];
    const float* proj_b = (const float*)d_in[8];
    const float* ln_g   = (const float*)d_in[9];
    const float* ln_b   = (const float*)d_in[10];
    const float* fc1_w  = (const float*)d_in[11];
    const float* fc1_b  = (const float*)d_in[12];
    const float* fc2_w  = (const float*)d_in[13];
    const float* fc2_b  = (const float*)d_in[14];
    float* out = (float*)d_out;

    __nv_bfloat16 *p_win, *p_qkv, *p_attn, *p_f, *p_hid, *p_wq, *p_wp, *p_w1, *p_w2;
    float *p_xtok, *p_y;
    cudaGetSymbolAddress((void**)&p_win, g_win);
    cudaGetSymbolAddress((void**)&p_qkv, g_qkv);
    cudaGetSymbolAddress((void**)&p_attn, g_attn);
    cudaGetSymbolAddress((void**)&p_f, g_f);
    cudaGetSymbolAddress((void**)&p_hid, g_hid);
    cudaGetSymbolAddress((void**)&p_wq, g_wq);
    cudaGetSymbolAddress((void**)&p_wp, g_wp);
    cudaGetSymbolAddress((void**)&p_w1, g_w1);
    cudaGetSymbolAddress((void**)&p_w2, g_w2);
    cudaGetSymbolAddress((void**)&p_xtok, g_xtok);
    cudaGetSymbolAddress((void**)&p_y, g_y);

    cudaFuncSetAttribute(attn_kernel, cudaFuncAttributeMaxDynamicSharedMemorySize, 50176);

    // 0. weight transpose + bf16
    wprep_kernel<<<768, 256>>>(qkv_w, proj_w, fc1_w, fc2_w);

    // 1. BN + window partition (bf16) + raw token copy (fp32)
    bn_window_kernel<<<dim3(896, 4, 4), 256>>>(x, bn_g, bn_b, bn_m, bn_v, p_win, p_xtok);

    // 2. QKV GEMM (HMMA bf16): (200704 x 128) @ (128 x 384)
    mma_gemm<128, 384, 0><<<dim3(3, 1568), 256>>>(p_win, p_wq, qkv_b, p_qkv, nullptr);

    // 3. Windowed attention
    attn_kernel<<<dim3(1024, 4), 224, 50176>>>(p_qkv, p_attn);

    // 4. Proj GEMM + window-reverse + residual -> g_y (fp32)
    mma_gemm<128, 128, 1><<<dim3(1, 1568), 256>>>(p_attn, p_wp, proj_b, p_y, p_xtok);

    // 5. LayerNorm -> bf16
    ln_kernel<<<25088, 256>>>(p_y, ln_g, ln_b, p_f);

    // 6. fc1 GEMM + exact GELU -> bf16 hidden
    mma_gemm<128, 512, 2><<<dim3(4, 1568), 256>>>(p_f, p_w1, fc1_b, p_hid, nullptr);

    // 7. fc2 GEMM + residual + transpose store -> out (B,C,T,H,W)
    mma_gemm<512, 128, 3><<<dim3(1, 1568), 256>>>(p_hid, p_w2, fc2_b, out, p_y);
}

// round 5
// speedup vs baseline: 4.2875x; 1.8806x over previous
#include <cuda_runtime.h>
#include <cuda_bf16.h>
#include <math.h>
#include <stdint.h>

// ---------------- problem constants ----------------
#define Bb   4
#define Cc   128
#define Tt   16
#define Hh   56
#define Ww   56
#define THW  50176      // Tt*Hh*Ww
#define TOK  200704     // Bb*THW
#define NTOK 196        // 4*7*7
#define HID  512
#define NPAD 208        // 13*16
#define SSTR 40         // smem row stride in bf16 (80B: conflict-free ldmatrix)

// ---------------- scratch (device globals) ----------------
__device__ __nv_bfloat16 g_win [(size_t)TOK * Cc];    // BN'd windows (bf16, window order)
__device__ __nv_bfloat16 g_qkv [(size_t)TOK * 384];   // qkv (bf16, window order)
__device__ __nv_bfloat16 g_attn[(size_t)TOK * Cc];    // attention out (bf16, window order)
__device__ __nv_bfloat16 g_f   [(size_t)TOK * Cc];    // LN out (bf16, token order)
__device__ __nv_bfloat16 g_hid [(size_t)TOK * HID];   // gelu(fc1) (bf16, token order)
__device__ float         g_xtok[(size_t)TOK * Cc];    // raw x (fp32, token order)
__device__ float         g_y   [(size_t)TOK * Cc];    // x + attn residual (fp32, token order)
// transposed bf16 weights [N][K]
__device__ __nv_bfloat16 g_wq[384 * 128];
__device__ __nv_bfloat16 g_wp[128 * 128];
__device__ __nv_bfloat16 g_w1[512 * 128];
__device__ __nv_bfloat16 g_w2[128 * 512];

// ---------------- helpers ----------------
__device__ __forceinline__ uint32_t smem_u32(const void* p) {
    uint32_t a;
    asm("{ .reg .u64 t; cvta.to.shared.u64 t, %1; cvt.u32.u64 %0, t; }" : "=r"(a) : "l"(p));
    return a;
}
__device__ __forceinline__ void ldsm4(uint32_t* r, uint32_t addr) {
    asm volatile("ldmatrix.sync.aligned.m8n8.x4.shared.b16 {%0,%1,%2,%3}, [%4];"
        : "=r"(r[0]), "=r"(r[1]), "=r"(r[2]), "=r"(r[3]) : "r"(addr));
}
__device__ __forceinline__ void ldsm4t(uint32_t* r, uint32_t addr) {
    asm volatile("ldmatrix.sync.aligned.m8n8.x4.trans.shared.b16 {%0,%1,%2,%3}, [%4];"
        : "=r"(r[0]), "=r"(r[1]), "=r"(r[2]), "=r"(r[3]) : "r"(addr));
}
__device__ __forceinline__ void mma_bf16(float* d, const uint32_t* a, uint32_t b0, uint32_t b1) {
    asm volatile(
        "mma.sync.aligned.m16n8k16.row.col.f32.bf16.bf16.f32 "
        "{%0,%1,%2,%3}, {%4,%5,%6,%7}, {%8,%9}, {%0,%1,%2,%3};"
        : "+f"(d[0]), "+f"(d[1]), "+f"(d[2]), "+f"(d[3])
        : "r"(a[0]), "r"(a[1]), "r"(a[2]), "r"(a[3]), "r"(b0), "r"(b1));
}
__device__ __forceinline__ uint32_t pk_bf2(float x, float y) {
    __nv_bfloat162 h = __floats2bfloat162_rn(x, y);
    return *(uint32_t*)&h;
}
__device__ __forceinline__ float gelu_exact(float v) {
    return 0.5f * v * (1.0f + erff(v * 0.7071067811865475f));
}

// ============================================================
// Weight transpose + bf16 convert: W[K][N] -> Wt[N][K] bf16
// ============================================================
__global__ __launch_bounds__(256) void wprep_kernel(
    const float* __restrict__ qkv_w, const float* __restrict__ proj_w,
    const float* __restrict__ fc1_w, const float* __restrict__ fc2_w)
{
    int i = blockIdx.x * 256 + threadIdx.x;
    if (i < 49152) {                       // qkv: 384x128
        int n = i >> 7, k = i & 127;
        g_wq[i] = __float2bfloat16_rn(qkv_w[k * 384 + n]);
    } else if (i < 65536) {                // proj: 128x128
        int j = i - 49152; int n = j >> 7, k = j & 127;
        g_wp[j] = __float2bfloat16_rn(proj_w[k * 128 + n]);
    } else if (i < 131072) {               // fc1: 512x128
        int j = i - 65536; int n = j >> 7, k = j & 127;
        g_w1[j] = __float2bfloat16_rn(fc1_w[k * 512 + n]);
    } else if (i < 196608) {               // fc2: 128x512
        int j = i - 131072; int n = j >> 9, k = j & 511;
        g_w2[j] = __float2bfloat16_rn(fc2_w[k * 128 + n]);
    }
}

// ============================================================
// BN + window partition (bf16) + token-major raw copy (fp32)
// ============================================================
__global__ __launch_bounds__(256) void bn_window_kernel(
    const float* __restrict__ x, const float* __restrict__ gamma,
    const float* __restrict__ beta, const float* __restrict__ mean,
    const float* __restrict__ var, __nv_bfloat16* __restrict__ win,
    float* __restrict__ xtok)
{
    __shared__ float rawS[32][57];
    __shared__ float bnS[32][57];
    const int gx = blockIdx.x;
    const int t = gx / 56, h = gx % 56;
    const int c0 = blockIdx.y * 32;
    const int b = blockIdx.z;
    const int tid = threadIdx.x;

#pragma unroll
    for (int it = 0; it < 7; it++) {
        int idx = tid + it * 256;
        int i = idx / 56, j = idx % 56;
        int c = c0 + i;
        size_t off = ((((size_t)b * Cc + c) * Tt + t) * Hh + h) * Ww + j;
        float v = x[off];
        rawS[i][j] = v;
        float inv = rsqrtf(var[c] + 1e-5f);
        bnS[i][j] = (v - mean[c]) * (inv * gamma[c]) + beta[c];
    }
    __syncthreads();

    const int tblk = t >> 2, wt = t & 3;
    const int hblk = h / 7, wh = h % 7;
#pragma unroll
    for (int it = 0; it < 7; it++) {
        int idx = tid + it * 256;
        int i = idx & 31, j = idx >> 5;
        int wblk = j / 7, ww2 = j % 7;
        int widx = ((b * 4 + tblk) * 8 + hblk) * 8 + wblk;
        int n = (wt * 7 + wh) * 7 + ww2;
        win[((size_t)widx * NTOK + n) * Cc + c0 + i] = __float2bfloat16_rn(bnS[i][j]);
        size_t tok = (size_t)b * THW + ((size_t)t * Hh + h) * Ww + j;
        xtok[tok * Cc + c0 + i] = rawS[i][j];
    }
}

// ============================================================
// bf16 HMMA GEMM (mma.sync.m16n8k16), CTA tile 128x128, 8 warps (4Mx2N),
// warp tile 32x64, K-chunk 64 in smem, fp32 accumulate.
// ============================================================
template<int KTOT, int NOUT, int EPI>
__global__ __launch_bounds__(256) void mma_gemm(
    const __nv_bfloat16* __restrict__ A, const __nv_bfloat16* __restrict__ Bm,
    const float* __restrict__ bias, void* __restrict__ outv,
    const float* __restrict__ res)
{
    __shared__ __nv_bfloat16 As[128][72];
    __shared__ __nv_bfloat16 Bs[128][72];
    const int tid = threadIdx.x;
    const int nb = blockIdx.x * 128;
    const int rb = blockIdx.y * 128;
    const int lane = tid & 31, wid = tid >> 5;
    const int wm = wid >> 1, wn = wid & 1;     // warp grid 4(M) x 2(N)

    float acc[2][8][4];
#pragma unroll
    for (int mt = 0; mt < 2; mt++)
#pragma unroll
        for (int nt = 0; nt < 8; nt++)
#pragma unroll
            for (int j = 0; j < 4; j++) acc[mt][nt][j] = 0.f;

    const int aRow = lane & 15, aKH = lane >> 4;
    const int bRow = ((lane >> 4) << 3) + (lane & 7);
    const int bKH = (lane >> 3) & 1;

    for (int k0 = 0; k0 < KTOT; k0 += 64) {
#pragma unroll
        for (int p = 0; p < 4; p++) {
            int idx = tid + p * 256;
            int row = idx >> 3, cc = idx & 7;
            *(uint4*)&As[row][cc * 8] =
                *(const uint4*)(A + (size_t)(rb + row) * KTOT + k0 + cc * 8);
            *(uint4*)&Bs[row][cc * 8] =
                *(const uint4*)(Bm + (size_t)(nb + row) * KTOT + k0 + cc * 8);
        }
        __syncthreads();

#pragma unroll
        for (int ks = 0; ks < 4; ks++) {
            const int kk = ks * 16;
            uint32_t a[2][4], b[4][4];
#pragma unroll
            for (int mt = 0; mt < 2; mt++)
                ldsm4(a[mt], smem_u32(&As[wm * 32 + mt * 16 + aRow][kk + aKH * 8]));
#pragma unroll
            for (int np = 0; np < 4; np++)
                ldsm4(b[np], smem_u32(&Bs[wn * 64 + np * 16 + bRow][kk + bKH * 8]));
#pragma unroll
            for (int mt = 0; mt < 2; mt++)
#pragma unroll
                for (int nt = 0; nt < 8; nt++)
                    mma_bf16(acc[mt][nt], a[mt], b[nt >> 1][(nt & 1) * 2],
                             b[nt >> 1][(nt & 1) * 2 + 1]);
        }
        __syncthreads();
    }

    // ---------------- epilogue ----------------
    const int gid = lane >> 2, tig = lane & 3;
#pragma unroll
    for (int mt = 0; mt < 2; mt++) {
#pragma unroll
        for (int half = 0; half < 2; half++) {
            const int R = rb + wm * 32 + mt * 16 + half * 8 + gid;

            if constexpr (EPI == 0 || EPI == 2) {
                __nv_bfloat16* po = (__nv_bfloat16*)outv + (size_t)R * NOUT;
#pragma unroll
                for (int nt = 0; nt < 8; nt++) {
                    int c = nb + wn * 64 + nt * 8 + tig * 2;
                    float v0 = acc[mt][nt][half * 2]     + bias[c];
                    float v1 = acc[mt][nt][half * 2 + 1] + bias[c + 1];
                    if constexpr (EPI == 2) { v0 = gelu_exact(v0); v1 = gelu_exact(v1); }
                    *(__nv_bfloat162*)(po + c) = __floats2bfloat162_rn(v0, v1);
                }
            } else if constexpr (EPI == 1) {
                unsigned r = (unsigned)R;
                unsigned widx = r / 196u, nl = r - widx * 196u;
                unsigned wblk = widx & 7u, hblk = (widx >> 3) & 7u;
                unsigned tblk = (widx >> 6) & 3u, bbx = widx >> 8;
                unsigned wt = nl / 49u, rem = nl - wt * 49u;
                unsigned wh = rem / 7u, w2 = rem - wh * 7u;
                unsigned th = tblk * 4 + wt, hp = hblk * 7 + wh, wp = wblk * 7 + w2;
                size_t tok = (size_t)bbx * THW + ((size_t)th * Hh + hp) * Ww + wp;
                float* po = (float*)outv + tok * Cc;
                const float* pr = res + tok * Cc;
#pragma unroll
                for (int nt = 0; nt < 8; nt++) {
                    int c = wn * 64 + nt * 8 + tig * 2;
                    float2 xr = *(const float2*)(pr + c);
                    float2 o;
                    o.x = acc[mt][nt][half * 2]     + bias[c]     + xr.x;
                    o.y = acc[mt][nt][half * 2 + 1] + bias[c + 1] + xr.y;
                    *(float2*)(po + c) = o;
                }
            } else {  // EPI == 3
                unsigned bq = (unsigned)R / (unsigned)THW;
                unsigned thw = (unsigned)R - bq * (unsigned)THW;
                const float* pr = res + (size_t)R * Cc;
                float* po = (float*)outv;
#pragma unroll
                for (int nt = 0; nt < 8; nt++) {
                    int c = wn * 64 + nt * 8 + tig * 2;
                    float2 xr = *(const float2*)(pr + c);
                    po[(size_t)(bq * Cc + c) * THW + thw] =
                        acc[mt][nt][half * 2] + bias[c] + xr.x;
                    po[(size_t)(bq * Cc + c + 1) * THW + thw] =
                        acc[mt][nt][half * 2 + 1] + bias[c + 1] + xr.y;
                }
            }
        }
    }
}

// ============================================================
// HMMA attention: one CTA per (window, head), 4 warps.
// Q/K/V bf16 in smem ([208][40], conflict-free ldmatrix).
// Per warp m-tile (16 rows): stream 13 key-blocks of 16:
//   S = Q K^T (4 mma), exp, mask cols>=196, pack P in-register,
//   O += P V (ldmatrix.trans b-frags, 4 mma). Normalize by row sum at end.
// ============================================================
__global__ __launch_bounds__(128) void attn_mma_kernel(
    const __nv_bfloat16* __restrict__ qkv, __nv_bfloat16* __restrict__ outp)
{
    extern __shared__ __nv_bfloat16 sb[];
    __nv_bfloat16* Qs = sb;                       // [208][40]
    __nv_bfloat16* Ks = sb + NPAD * SSTR;
    __nv_bfloat16* Vs = sb + 2 * NPAD * SSTR;
    const int widx = blockIdx.x, hh = blockIdx.y;
    const size_t base = (size_t)widx * NTOK * 384 + hh * 32;
    const int tid = threadIdx.x;
    const int lane = tid & 31, wid = tid >> 5;

    // stage Q,K,V (196 rows x 32 bf16) as 4B words
    for (int idx = tid; idx < 3136; idx += 128) {
        int row = idx >> 4, u = idx & 15;
        const uint32_t* src = (const uint32_t*)(qkv + base + (size_t)row * 384);
        *(uint32_t*)(Qs + row * SSTR + u * 2) = src[u];
        *(uint32_t*)(Ks + row * SSTR + u * 2) = src[64 + u];
        *(uint32_t*)(Vs + row * SSTR + u * 2) = src[128 + u];
    }
    // zero K,V pad rows (196..207); garbage Q pad only affects unstored rows
    for (int idx = tid; idx < 12 * 16; idx += 128) {
        int row = 196 + (idx >> 4), u = idx & 15;
        *(uint32_t*)(Ks + row * SSTR + u * 2) = 0;
        *(uint32_t*)(Vs + row * SSTR + u * 2) = 0;
    }
    __syncthreads();

    const int g = lane >> 2, tig = lane & 3;
    const int aRow = lane & 15, aKH = lane >> 4;
    const int bRow = ((lane >> 4) << 3) + (lane & 7), bKH = (lane >> 3) & 1;
    const int vKrow = (lane & 7) + ((lane >> 3) & 1) * 8;
    const int vNh = ((lane >> 4) & 1) * 8;
    const float sc = 0.17677669529663688f;    // 1/sqrt(32)

    for (int mt = wid; mt < 13; mt += 4) {
        const int m0 = mt * 16;
        uint32_t qa[2][4];
        ldsm4(qa[0], smem_u32(Qs + (m0 + aRow) * SSTR + aKH * 8));
        ldsm4(qa[1], smem_u32(Qs + (m0 + aRow) * SSTR + 16 + aKH * 8));

        float oacc[4][4];
#pragma unroll
        for (int nt = 0; nt < 4; nt++)
#pragma unroll
            for (int j = 0; j < 4; j++) oacc[nt][j] = 0.f;
        float rs0 = 0.f, rs1 = 0.f;

        for (int ks = 0; ks < 13; ks++) {
            uint32_t kb0[4], kb1[4];
            ldsm4(kb0, smem_u32(Ks + (ks * 16 + bRow) * SSTR + bKH * 8));
            ldsm4(kb1, smem_u32(Ks + (ks * 16 + bRow) * SSTR + 16 + bKH * 8));

            float s0[4] = {0.f, 0.f, 0.f, 0.f}, s1[4] = {0.f, 0.f, 0.f, 0.f};
            mma_bf16(s0, qa[0], kb0[0], kb0[1]);   // sub0 (cols ks*16+0..7), k 0-15
            mma_bf16(s0, qa[1], kb1[0], kb1[1]);   //                       k 16-31
            mma_bf16(s1, qa[0], kb0[2], kb0[3]);   // sub1 (cols ks*16+8..15)
            mma_bf16(s1, qa[1], kb1[2], kb1[3]);

            float e0[4], e1[4];
#pragma unroll
            for (int j = 0; j < 4; j++) {
                e0[j] = __expf(s0[j] * sc);
                e1[j] = __expf(s1[j] * sc);
            }
            if (ks == 12) {                         // mask cols >= 196
#pragma unroll
                for (int j = 0; j < 4; j++) e1[j] = 0.f;     // cols 200-207
                if (tig >= 2) {                              // cols 196-199
#pragma unroll
                    for (int j = 0; j < 4; j++) e0[j] = 0.f;
                }
            }
            rs0 += e0[0] + e0[1] + e1[0] + e1[1];   // row g
            rs1 += e0[2] + e0[3] + e1[2] + e1[3];   // row g+8

            // pack P d-frags into a-frags (layout-compatible)
            uint32_t pa[4];
            pa[0] = pk_bf2(e0[0], e0[1]);
            pa[1] = pk_bf2(e0[2], e0[3]);
            pa[2] = pk_bf2(e1[0], e1[1]);
            pa[3] = pk_bf2(e1[2], e1[3]);

            // O += P V   (V [token][dim] -> b-frags via ldmatrix.trans)
            uint32_t vb0[4], vb1[4];
            uint32_t va = smem_u32(Vs + (ks * 16 + vKrow) * SSTR + vNh);
            ldsm4t(vb0, va);          // head-dim cols 0-15
            ldsm4t(vb1, va + 32);     // head-dim cols 16-31 (+16 bf16)
            mma_bf16(oacc[0], pa, vb0[0], vb0[1]);
            mma_bf16(oacc[1], pa, vb0[2], vb0[3]);
            mma_bf16(oacc[2], pa, vb1[0], vb1[1]);
            mma_bf16(oacc[3], pa, vb1[2], vb1[3]);
        }

        // reduce row sums across the tig quad
        rs0 += __shfl_xor_sync(0xffffffffu, rs0, 1);
        rs0 += __shfl_xor_sync(0xffffffffu, rs0, 2);
        rs1 += __shfl_xor_sync(0xffffffffu, rs1, 1);
        rs1 += __shfl_xor_sync(0xffffffffu, rs1, 2);
        float i0 = 1.f / rs0, i1 = 1.f / rs1;

        const int r0 = m0 + g, r1 = m0 + g + 8;
        if (r0 < NTOK) {
            __nv_bfloat16* p = outp + ((size_t)widx * NTOK + r0) * Cc + hh * 32 + tig * 2;
#pragma unroll
            for (int nt = 0; nt < 4; nt++)
                *(__nv_bfloat162*)(p + nt * 8) =
                    __floats2bfloat162_rn(oacc[nt][0] * i0, oacc[nt][1] * i0);
        }
        if (r1 < NTOK) {
            __nv_bfloat16* p = outp + ((size_t)widx * NTOK + r1) * Cc + hh * 32 + tig * 2;
#pragma unroll
            for (int nt = 0; nt < 4; nt++)
                *(__nv_bfloat162*)(p + nt * 8) =
                    __floats2bfloat162_rn(oacc[nt][2] * i1, oacc[nt][3] * i1);
        }
    }
}

// ============================================================
// LayerNorm: one warp per token, fp32 in -> bf16 out
// ============================================================
__global__ __launch_bounds__(256) void ln_kernel(
    const float* __restrict__ y, const float* __restrict__ g,
    const float* __restrict__ bt, __nv_bfloat16* __restrict__ f)
{
    const int warp = threadIdx.x >> 5, lane = threadIdx.x & 31;
    const size_t tok = (size_t)blockIdx.x * 8 + warp;
    const float4 v = *(const float4*)&y[tok * Cc + lane * 4];
    float sum = v.x + v.y + v.z + v.w;
#pragma unroll
    for (int o = 16; o > 0; o >>= 1) sum += __shfl_xor_sync(0xffffffffu, sum, o);
    float mu = sum * (1.f / 128.f);
    float dx = v.x - mu, dy = v.y - mu, dz = v.z - mu, dw = v.w - mu;
    float sq = dx * dx + dy * dy + dz * dz + dw * dw;
#pragma unroll
    for (int o = 16; o > 0; o >>= 1) sq += __shfl_xor_sync(0xffffffffu, sq, o);
    float inv = rsqrtf(sq * (1.f / 128.f) + 1e-5f);
    float4 gg = *(const float4*)&g[lane * 4];
    float4 bb = *(const float4*)&bt[lane * 4];
    __nv_bfloat16* po = f + tok * Cc + lane * 4;
    *(__nv_bfloat162*)(po)     = __floats2bfloat162_rn(dx * inv * gg.x + bb.x, dy * inv * gg.y + bb.y);
    *(__nv_bfloat162*)(po + 2) = __floats2bfloat162_rn(dz * inv * gg.z + bb.z, dw * inv * gg.w + bb.w);
}

// ============================================================
// Launch
// ============================================================
extern "C" void kernel_launch(void* const* d_in, const int* in_sizes, int n_in,
                              void* d_out, int out_size)
{
    const float* x      = (const float*)d_in[0];
    const float* bn_g   = (const float*)d_in[1];
    const float* bn_b   = (const float*)d_in[2];
    const float* bn_m   = (const float*)d_in[3];
    const float* bn_v   = (const float*)d_in[4];
    const float* qkv_w  = (const float*)d_in[5];
    const float* qkv_b  = (const float*)d_in[6];
    const float* proj_w = (const float*)d_in[7];
    const float* proj_b = (const float*)d_in[8];
    const float* ln_g   = (const float*)d_in[9];
    const float* ln_b   = (const float*)d_in[10];
    const float* fc1_w  = (const float*)d_in[11];
    const float* fc1_b  = (const float*)d_in[12];
    const float* fc2_w  = (const float*)d_in[13];
    const float* fc2_b  = (const float*)d_in[14];
    float* out = (float*)d_out;

    __nv_bfloat16 *p_win, *p_qkv, *p_attn, *p_f, *p_hid, *p_wq, *p_wp, *p_w1, *p_w2;
    float *p_xtok, *p_y;
    cudaGetSymbolAddress((void**)&p_win, g_win);
    cudaGetSymbolAddress((void**)&p_qkv, g_qkv);
    cudaGetSymbolAddress((void**)&p_attn, g_attn);
    cudaGetSymbolAddress((void**)&p_f, g_f);
    cudaGetSymbolAddress((void**)&p_hid, g_hid);
    cudaGetSymbolAddress((void**)&p_wq, g_wq);
    cudaGetSymbolAddress((void**)&p_wp, g_wp);
    cudaGetSymbolAddress((void**)&p_w1, g_w1);
    cudaGetSymbolAddress((void**)&p_w2, g_w2);
    cudaGetSymbolAddress((void**)&p_xtok, g_xtok);
    cudaGetSymbolAddress((void**)&p_y, g_y);

    const int ASM = NPAD * SSTR * 3 * 2;   // 49920 B
    cudaFuncSetAttribute(attn_mma_kernel, cudaFuncAttributeMaxDynamicSharedMemorySize, ASM);

    // 0. weight transpose + bf16
    wprep_kernel<<<768, 256>>>(qkv_w, proj_w, fc1_w, fc2_w);

    // 1. BN + window partition (bf16) + raw token copy (fp32)
    bn_window_kernel<<<dim3(896, 4, 4), 256>>>(x, bn_g, bn_b, bn_m, bn_v, p_win, p_xtok);

    // 2. QKV GEMM (HMMA bf16): (200704 x 128) @ (128 x 384)
    mma_gemm<128, 384, 0><<<dim3(3, 1568), 256>>>(p_win, p_wq, qkv_b, p_qkv, nullptr);

    // 3. Windowed attention (HMMA)
    attn_mma_kernel<<<dim3(1024, 4), 128, ASM>>>(p_qkv, p_attn);

    // 4. Proj GEMM + window-reverse + residual -> g_y (fp32)
    mma_gemm<128, 128, 1><<<dim3(1, 1568), 256>>>(p_attn, p_wp, proj_b, p_y, p_xtok);

    // 5. LayerNorm -> bf16
    ln_kernel<<<25088, 256>>>(p_y, ln_g, ln_b, p_f);

    // 6. fc1 GEMM + exact GELU -> bf16 hidden
    mma_gemm<128, 512, 2><<<dim3(4, 1568), 256>>>(p_f, p_w1, fc1_b, p_hid, nullptr);

    // 7. fc2 GEMM + residual + transpose store -> out (B,C,T,H,W)
    mma_gemm<512, 128, 3><<<dim3(1, 1568), 256>>>(p_hid, p_w2, fc2_b, out, p_y);
}

// round 8
// speedup vs baseline: 4.6692x; 1.0890x over previous
#include <cuda_runtime.h>
#include <cuda_bf16.h>
#include <math.h>
#include <stdint.h>

// ---------------- problem constants ----------------
#define Bb   4
#define Cc   128
#define Tt   16
#define Hh   56
#define Ww   56
#define THW  50176      // Tt*Hh*Ww
#define TOK  200704     // Bb*THW
#define NTOK 196        // 4*7*7
#define HID  512
#define NPAD 208        // 13*16
#define SSTR 40         // smem row stride in bf16 (80B: conflict-free ldmatrix)

// ---------------- scratch (device globals) ----------------
__device__ __nv_bfloat16 g_win [(size_t)TOK * Cc];    // BN'd windows (bf16, window order)
__device__ __nv_bfloat16 g_qkv [(size_t)TOK * 384];   // qkv (bf16, window order)
__device__ __nv_bfloat16 g_attn[(size_t)TOK * Cc];    // attention out (bf16, window order)
__device__ __nv_bfloat16 g_f   [(size_t)TOK * Cc];    // LN out (bf16, token order)
__device__ __nv_bfloat16 g_hid [(size_t)TOK * HID];   // gelu(fc1) (bf16, token order)
__device__ float         g_xtok[(size_t)TOK * Cc];    // raw x (fp32, token order)
__device__ float         g_y   [(size_t)TOK * Cc];    // x + attn residual (fp32, token order)
// transposed bf16 weights [N][K]
__device__ __nv_bfloat16 g_wq[384 * 128];
__device__ __nv_bfloat16 g_wp[128 * 128];
__device__ __nv_bfloat16 g_w1[512 * 128];
__device__ __nv_bfloat16 g_w2[128 * 512];

// ---------------- helpers ----------------
__device__ __forceinline__ uint32_t smem_u32(const void* p) {
    uint32_t a;
    asm("{ .reg .u64 t; cvta.to.shared.u64 t, %1; cvt.u32.u64 %0, t; }" : "=r"(a) : "l"(p));
    return a;
}
__device__ __forceinline__ void ldsm4(uint32_t* r, uint32_t addr) {
    asm volatile("ldmatrix.sync.aligned.m8n8.x4.shared.b16 {%0,%1,%2,%3}, [%4];"
        : "=r"(r[0]), "=r"(r[1]), "=r"(r[2]), "=r"(r[3]) : "r"(addr));
}
__device__ __forceinline__ void ldsm4t(uint32_t* r, uint32_t addr) {
    asm volatile("ldmatrix.sync.aligned.m8n8.x4.trans.shared.b16 {%0,%1,%2,%3}, [%4];"
        : "=r"(r[0]), "=r"(r[1]), "=r"(r[2]), "=r"(r[3]) : "r"(addr));
}
__device__ __forceinline__ void mma_bf16(float* d, const uint32_t* a, uint32_t b0, uint32_t b1) {
    asm volatile(
        "mma.sync.aligned.m16n8k16.row.col.f32.bf16.bf16.f32 "
        "{%0,%1,%2,%3}, {%4,%5,%6,%7}, {%8,%9}, {%0,%1,%2,%3};"
        : "+f"(d[0]), "+f"(d[1]), "+f"(d[2]), "+f"(d[3])
        : "r"(a[0]), "r"(a[1]), "r"(a[2]), "r"(a[3]), "r"(b0), "r"(b1));
}
__device__ __forceinline__ uint32_t pk_bf2(float x, float y) {
    __nv_bfloat162 h = __floats2bfloat162_rn(x, y);
    return *(uint32_t*)&h;
}
__device__ __forceinline__ float gelu_exact(float v) {
    return 0.5f * v * (1.0f + erff(v * 0.7071067811865475f));
}
__device__ __forceinline__ void cpa16(uint32_t dst, const void* src) {
    asm volatile("cp.async.cg.shared.global [%0], [%1], 16;" :: "r"(dst), "l"(src));
}

// ============================================================
// Weight transpose + bf16 convert: W[K][N] -> Wt[N][K] bf16
// ============================================================
__global__ __launch_bounds__(256) void wprep_kernel(
    const float* __restrict__ qkv_w, const float* __restrict__ proj_w,
    const float* __restrict__ fc1_w, const float* __restrict__ fc2_w)
{
    int i = blockIdx.x * 256 + threadIdx.x;
    if (i < 49152) {                       // qkv: 384x128
        int n = i >> 7, k = i & 127;
        g_wq[i] = __float2bfloat16_rn(qkv_w[k * 384 + n]);
    } else if (i < 65536) {                // proj: 128x128
        int j = i - 49152; int n = j >> 7, k = j & 127;
        g_wp[j] = __float2bfloat16_rn(proj_w[k * 128 + n]);
    } else if (i < 131072) {               // fc1: 512x128
        int j = i - 65536; int n = j >> 7, k = j & 127;
        g_w1[j] = __float2bfloat16_rn(fc1_w[k * 512 + n]);
    } else if (i < 196608) {               // fc2: 128x512
        int j = i - 131072; int n = j >> 9, k = j & 511;
        g_w2[j] = __float2bfloat16_rn(fc2_w[k * 128 + n]);
    }
}

// ============================================================
// BN + window partition (bf16) + token-major raw copy (fp32)
// ============================================================
__global__ __launch_bounds__(256) void bn_window_kernel(
    const float* __restrict__ x, const float* __restrict__ gamma,
    const float* __restrict__ beta, const float* __restrict__ mean,
    const float* __restrict__ var, __nv_bfloat16* __restrict__ win,
    float* __restrict__ xtok)
{
    __shared__ float rawS[32][57];
    __shared__ float bnS[32][57];
    const int gx = blockIdx.x;
    const int t = gx / 56, h = gx % 56;
    const int c0 = blockIdx.y * 32;
    const int b = blockIdx.z;
    const int tid = threadIdx.x;

#pragma unroll
    for (int it = 0; it < 7; it++) {
        int idx = tid + it * 256;
        int i = idx / 56, j = idx % 56;
        int c = c0 + i;
        size_t off = ((((size_t)b * Cc + c) * Tt + t) * Hh + h) * Ww + j;
        float v = x[off];
        rawS[i][j] = v;
        float inv = rsqrtf(var[c] + 1e-5f);
        bnS[i][j] = (v - mean[c]) * (inv * gamma[c]) + beta[c];
    }
    __syncthreads();

    const int tblk = t >> 2, wt = t & 3;
    const int hblk = h / 7, wh = h % 7;
#pragma unroll
    for (int it = 0; it < 7; it++) {
        int idx = tid + it * 256;
        int i = idx & 31, j = idx >> 5;
        int wblk = j / 7, ww2 = j % 7;
        int widx = ((b * 4 + tblk) * 8 + hblk) * 8 + wblk;
        int n = (wt * 7 + wh) * 7 + ww2;
        win[((size_t)widx * NTOK + n) * Cc + c0 + i] = __float2bfloat16_rn(bnS[i][j]);
        size_t tok = (size_t)b * THW + ((size_t)t * Hh + h) * Ww + j;
        xtok[tok * Cc + c0 + i] = rawS[i][j];
    }
}

// ============================================================
// bf16 HMMA GEMM, CTA tile 128x128, 8 warps (4Mx2N), warp tile 32x64.
// cp.async 2-stage pipeline, K-chunk 32, double-buffered dynamic smem (40KB).
// EPI 0: bf16 +bias (qkv)
// EPI 1: fp32 +bias+res window->token scatter (proj) + FUSED LayerNorm -> fout bf16
// EPI 2: gelu->bf16 (fc1)
// EPI 3: fp32 +bias+res, transpose store (B,C,THW) (fc2)
// ============================================================
template<int KTOT, int NOUT, int EPI>
__global__ __launch_bounds__(256) void mma_gemm(
    const __nv_bfloat16* __restrict__ A, const __nv_bfloat16* __restrict__ Bm,
    const float* __restrict__ bias, void* __restrict__ outv,
    const float* __restrict__ res,
    const float* __restrict__ lng, const float* __restrict__ lnb,
    __nv_bfloat16* __restrict__ fout)
{
    extern __shared__ char dsm[];
    const uint32_t sA = smem_u32(dsm);            // [2][128][40] bf16
    const uint32_t sB = sA + 20480;               // [2][128][40] bf16
    const int tid = threadIdx.x;
    const int nb = blockIdx.x * 128;
    const int rb = blockIdx.y * 128;
    const int lane = tid & 31, wid = tid >> 5;
    const int wm = wid >> 1, wn = wid & 1;        // warp grid 4(M) x 2(N)

    float acc[2][8][4];
#pragma unroll
    for (int mt = 0; mt < 2; mt++)
#pragma unroll
        for (int nt = 0; nt < 8; nt++)
#pragma unroll
            for (int j = 0; j < 4; j++) acc[mt][nt][j] = 0.f;

    const int aRow = lane & 15, aKH = lane >> 4;
    const int bRow = ((lane >> 4) << 3) + (lane & 7);
    const int bKH = (lane >> 3) & 1;
    const int ldRow = tid >> 2, ldC = tid & 3;    // cp.async coords

    auto preload = [&](int ch) {
        const int b = ch & 1, k0 = ch * 32;
#pragma unroll
        for (int p = 0; p < 2; p++) {
            int row = ldRow + p * 64;
            uint32_t off = (uint32_t)(b * 10240 + row * 80 + ldC * 16);
            cpa16(sA + off, A + (size_t)(rb + row) * KTOT + k0 + ldC * 8);
            cpa16(sB + off, Bm + (size_t)(nb + row) * KTOT + k0 + ldC * 8);
        }
        asm volatile("cp.async.commit_group;");
    };

    constexpr int CH = KTOT / 32;
    preload(0);
    for (int ch = 0; ch < CH; ch++) {
        if (ch + 1 < CH) {
            preload(ch + 1);
            asm volatile("cp.async.wait_group 1;");
        } else {
            asm volatile("cp.async.wait_group 0;");
        }
        __syncthreads();
        const uint32_t bA = sA + (ch & 1) * 10240;
        const uint32_t bB = sB + (ch & 1) * 10240;
#pragma unroll
        for (int ks = 0; ks < 2; ks++) {
            const int kk = ks * 16;
            uint32_t a[2][4], b[4][4];
#pragma unroll
            for (int mt = 0; mt < 2; mt++)
                ldsm4(a[mt], bA + (wm * 32 + mt * 16 + aRow) * 80 + (kk + aKH * 8) * 2);
#pragma unroll
            for (int np = 0; np < 4; np++)
                ldsm4(b[np], bB + (wn * 64 + np * 16 + bRow) * 80 + (kk + bKH * 8) * 2);
#pragma unroll
            for (int mt = 0; mt < 2; mt++)
#pragma unroll
                for (int nt = 0; nt < 8; nt++)
                    mma_bf16(acc[mt][nt], a[mt], b[nt >> 1][(nt & 1) * 2],
                             b[nt >> 1][(nt & 1) * 2 + 1]);
        }
        __syncthreads();
    }

    // ---------------- epilogue ----------------
    const int gid = lane >> 2, tig = lane & 3;

    if constexpr (EPI == 0 || EPI == 2) {
#pragma unroll
        for (int mt = 0; mt < 2; mt++) {
#pragma unroll
            for (int half = 0; half < 2; half++) {
                const int R = rb + wm * 32 + mt * 16 + half * 8 + gid;
                __nv_bfloat16* po = (__nv_bfloat16*)outv + (size_t)R * NOUT;
#pragma unroll
                for (int nt = 0; nt < 8; nt++) {
                    int c = nb + wn * 64 + nt * 8 + tig * 2;
                    float v0 = acc[mt][nt][half * 2]     + bias[c];
                    float v1 = acc[mt][nt][half * 2 + 1] + bias[c + 1];
                    if constexpr (EPI == 2) { v0 = gelu_exact(v0); v1 = gelu_exact(v1); }
                    *(__nv_bfloat162*)(po + c) = __floats2bfloat162_rn(v0, v1);
                }
            }
        }
    } else if constexpr (EPI == 1) {
        // proj + residual + fused LayerNorm
        size_t toks[2][2];
        float rsum[2][2], rsq[2][2];
#pragma unroll
        for (int mt = 0; mt < 2; mt++) {
#pragma unroll
            for (int half = 0; half < 2; half++) {
                const int R = rb + wm * 32 + mt * 16 + half * 8 + gid;
                unsigned r = (unsigned)R;
                unsigned widx = r / 196u, nl = r - widx * 196u;
                unsigned wblk = widx & 7u, hblk = (widx >> 3) & 7u;
                unsigned tblk = (widx >> 6) & 3u, bbx = widx >> 8;
                unsigned wt = nl / 49u, rem = nl - wt * 49u;
                unsigned wh = rem / 7u, w2 = rem - wh * 7u;
                unsigned th = tblk * 4 + wt, hp = hblk * 7 + wh, wp = wblk * 7 + w2;
                size_t tok = (size_t)bbx * THW + ((size_t)th * Hh + hp) * Ww + wp;
                toks[mt][half] = tok;
                float* po = (float*)outv + tok * Cc;
                const float* pr = res + tok * Cc;
                float s = 0.f, q = 0.f;
#pragma unroll
                for (int nt = 0; nt < 8; nt++) {
                    int c = wn * 64 + nt * 8 + tig * 2;
                    float2 xr = *(const float2*)(pr + c);
                    float y0 = acc[mt][nt][half * 2]     + bias[c]     + xr.x;
                    float y1 = acc[mt][nt][half * 2 + 1] + bias[c + 1] + xr.y;
                    acc[mt][nt][half * 2]     = y0;
                    acc[mt][nt][half * 2 + 1] = y1;
                    float2 o; o.x = y0; o.y = y1;
                    *(float2*)(po + c) = o;
                    s += y0 + y1;
                    q += y0 * y0 + y1 * y1;
                }
                rsum[mt][half] = s; rsq[mt][half] = q;
            }
        }
#pragma unroll
        for (int mt = 0; mt < 2; mt++)
#pragma unroll
            for (int half = 0; half < 2; half++) {
                rsum[mt][half] += __shfl_xor_sync(0xffffffffu, rsum[mt][half], 1);
                rsum[mt][half] += __shfl_xor_sync(0xffffffffu, rsum[mt][half], 2);
                rsq[mt][half]  += __shfl_xor_sync(0xffffffffu, rsq[mt][half], 1);
                rsq[mt][half]  += __shfl_xor_sync(0xffffffffu, rsq[mt][half], 2);
            }
        float2* red = (float2*)dsm;              // [128][2] (reuses GEMM smem)
        __syncthreads();
        if (tig == 0) {
#pragma unroll
            for (int mt = 0; mt < 2; mt++)
#pragma unroll
                for (int half = 0; half < 2; half++) {
                    int r = wm * 32 + mt * 16 + half * 8 + gid;
                    float2 v; v.x = rsum[mt][half]; v.y = rsq[mt][half];
                    red[r * 2 + wn] = v;
                }
        }
        __syncthreads();
#pragma unroll
        for (int mt = 0; mt < 2; mt++) {
#pragma unroll
            for (int half = 0; half < 2; half++) {
                int r = wm * 32 + mt * 16 + half * 8 + gid;
                float2 p0 = red[r * 2], p1 = red[r * 2 + 1];
                float mu = (p0.x + p1.x) * (1.f / 128.f);
                float var = (p0.y + p1.y) * (1.f / 128.f) - mu * mu;
                float inv = rsqrtf(var + 1e-5f);
                __nv_bfloat16* pf = fout + toks[mt][half] * Cc;
#pragma unroll
                for (int nt = 0; nt < 8; nt++) {
                    int c = wn * 64 + nt * 8 + tig * 2;
                    float2 gg = *(const float2*)(lng + c);
                    float2 bb = *(const float2*)(lnb + c);
                    float f0 = (acc[mt][nt][half * 2]     - mu) * inv * gg.x + bb.x;
                    float f1 = (acc[mt][nt][half * 2 + 1] - mu) * inv * gg.y + bb.y;
                    *(__nv_bfloat162*)(pf + c) = __floats2bfloat162_rn(f0, f1);
                }
            }
        }
    } else {  // EPI == 3
#pragma unroll
        for (int mt = 0; mt < 2; mt++) {
#pragma unroll
            for (int half = 0; half < 2; half++) {
                const int R = rb + wm * 32 + mt * 16 + half * 8 + gid;
                unsigned bq = (unsigned)R / (unsigned)THW;
                unsigned thw = (unsigned)R - bq * (unsigned)THW;
                const float* pr = res + (size_t)R * Cc;
                float* po = (float*)outv;
#pragma unroll
                for (int nt = 0; nt < 8; nt++) {
                    int c = wn * 64 + nt * 8 + tig * 2;
                    float2 xr = *(const float2*)(pr + c);
                    po[(size_t)(bq * Cc + c) * THW + thw] =
                        acc[mt][nt][half * 2] + bias[c] + xr.x;
                    po[(size_t)(bq * Cc + c + 1) * THW + thw] =
                        acc[mt][nt][half * 2 + 1] + bias[c + 1] + xr.y;
                }
            }
        }
    }
}

// ============================================================
// HMMA attention: one CTA per (window, head), 4 warps.
// K/V bf16 in static smem; Q a-frags loaded directly from gmem (rows clamped).
// ============================================================
__global__ __launch_bounds__(128) void attn_mma_kernel(
    const __nv_bfloat16* __restrict__ qkv, __nv_bfloat16* __restrict__ outp)
{
    __shared__ __nv_bfloat16 Ks[NPAD * SSTR];
    __shared__ __nv_bfloat16 Vs[NPAD * SSTR];
    const int widx = blockIdx.x, hh = blockIdx.y;
    const size_t base = (size_t)widx * NTOK * 384 + hh * 32;
    const int tid = threadIdx.x;
    const int lane = tid & 31, wid = tid >> 5;

    for (int idx = tid; idx < 3136; idx += 128) {
        int row = idx >> 4, u = idx & 15;
        const uint32_t* src = (const uint32_t*)(qkv + base + (size_t)row * 384);
        *(uint32_t*)(Ks + row * SSTR + u * 2) = src[64 + u];
        *(uint32_t*)(Vs + row * SSTR + u * 2) = src[128 + u];
    }
    for (int idx = tid; idx < 12 * 16; idx += 128) {
        int row = 196 + (idx >> 4), u = idx & 15;
        *(uint32_t*)(Ks + row * SSTR + u * 2) = 0;
        *(uint32_t*)(Vs + row * SSTR + u * 2) = 0;
    }
    __syncthreads();

    const int g = lane >> 2, tig = lane & 3;
    const int bRow = ((lane >> 4) << 3) + (lane & 7), bKH = (lane >> 3) & 1;
    const int vKrow = (lane & 7) + ((lane >> 3) & 1) * 8;
    const int vNh = ((lane >> 4) & 1) * 8;
    const float sc = 0.17677669529663688f;    // 1/sqrt(32)

    for (int mt = wid; mt < 13; mt += 4) {
        const int m0 = mt * 16;
        int r0 = m0 + g;     if (r0 > 195) r0 = 195;
        int r1 = m0 + g + 8; if (r1 > 195) r1 = 195;
        const __nv_bfloat16* q0 = qkv + base + (size_t)r0 * 384 + tig * 2;
        const __nv_bfloat16* q1 = qkv + base + (size_t)r1 * 384 + tig * 2;
        uint32_t qa[2][4];
        qa[0][0] = *(const uint32_t*)(q0);
        qa[0][1] = *(const uint32_t*)(q1);
        qa[0][2] = *(const uint32_t*)(q0 + 8);
        qa[0][3] = *(const uint32_t*)(q1 + 8);
        qa[1][0] = *(const uint32_t*)(q0 + 16);
        qa[1][1] = *(const uint32_t*)(q1 + 16);
        qa[1][2] = *(const uint32_t*)(q0 + 24);
        qa[1][3] = *(const uint32_t*)(q1 + 24);

        float oacc[4][4];
#pragma unroll
        for (int nt = 0; nt < 4; nt++)
#pragma unroll
            for (int j = 0; j < 4; j++) oacc[nt][j] = 0.f;
        float rs0 = 0.f, rs1 = 0.f;

        for (int ks = 0; ks < 13; ks++) {
            uint32_t kb0[4], kb1[4];
            ldsm4(kb0, smem_u32(Ks + (ks * 16 + bRow) * SSTR + bKH * 8));
            ldsm4(kb1, smem_u32(Ks + (ks * 16 + bRow) * SSTR + 16 + bKH * 8));

            float s0[4] = {0.f, 0.f, 0.f, 0.f}, s1[4] = {0.f, 0.f, 0.f, 0.f};
            mma_bf16(s0, qa[0], kb0[0], kb0[1]);
            mma_bf16(s0, qa[1], kb1[0], kb1[1]);
            mma_bf16(s1, qa[0], kb0[2], kb0[3]);
            mma_bf16(s1, qa[1], kb1[2], kb1[3]);

            float e0[4], e1[4];
#pragma unroll
            for (int j = 0; j < 4; j++) {
                e0[j] = __expf(s0[j] * sc);
                e1[j] = __expf(s1[j] * sc);
            }
            if (ks == 12) {
#pragma unroll
                for (int j = 0; j < 4; j++) e1[j] = 0.f;
                if (tig >= 2) {
#pragma unroll
                    for (int j = 0; j < 4; j++) e0[j] = 0.f;
                }
            }
            rs0 += e0[0] + e0[1] + e1[0] + e1[1];
            rs1 += e0[2] + e0[3] + e1[2] + e1[3];

            uint32_t pa[4];
            pa[0] = pk_bf2(e0[0], e0[1]);
            pa[1] = pk_bf2(e0[2], e0[3]);
            pa[2] = pk_bf2(e1[0], e1[1]);
            pa[3] = pk_bf2(e1[2], e1[3]);

            uint32_t vb0[4], vb1[4];
            uint32_t va = smem_u32(Vs + (ks * 16 + vKrow) * SSTR + vNh);
            ldsm4t(vb0, va);
            ldsm4t(vb1, va + 32);
            mma_bf16(oacc[0], pa, vb0[0], vb0[1]);
            mma_bf16(oacc[1], pa, vb0[2], vb0[3]);
            mma_bf16(oacc[2], pa, vb1[0], vb1[1]);
            mma_bf16(oacc[3], pa, vb1[2], vb1[3]);
        }

        rs0 += __shfl_xor_sync(0xffffffffu, rs0, 1);
        rs0 += __shfl_xor_sync(0xffffffffu, rs0, 2);
        rs1 += __shfl_xor_sync(0xffffffffu, rs1, 1);
        rs1 += __shfl_xor_sync(0xffffffffu, rs1, 2);
        float i0 = 1.f / rs0, i1 = 1.f / rs1;

        const int w0 = m0 + g, w1 = m0 + g + 8;
        if (w0 < NTOK) {
            __nv_bfloat16* p = outp + ((size_t)widx * NTOK + w0) * Cc + hh * 32 + tig * 2;
#pragma unroll
            for (int nt = 0; nt < 4; nt++)
                *(__nv_bfloat162*)(p + nt * 8) =
                    __floats2bfloat162_rn(oacc[nt][0] * i0, oacc[nt][1] * i0);
        }
        if (w1 < NTOK) {
            __nv_bfloat16* p = outp + ((size_t)widx * NTOK + w1) * Cc + hh * 32 + tig * 2;
#pragma unroll
            for (int nt = 0; nt < 4; nt++)
                *(__nv_bfloat162*)(p + nt * 8) =
                    __floats2bfloat162_rn(oacc[nt][2] * i1, oacc[nt][3] * i1);
        }
    }
}

// ============================================================
// Launch
// ============================================================
extern "C" void kernel_launch(void* const* d_in, const int* in_sizes, int n_in,
                              void* d_out, int out_size)
{
    const float* x      = (const float*)d_in[0];
    const float* bn_g   = (const float*)d_in[1];
    const float* bn_b   = (const float*)d_in[2];
    const float* bn_m   = (const float*)d_in[3];
    const float* bn_v   = (const float*)d_in[4];
    const float* qkv_w  = (const float*)d_in[5];
    const float* qkv_b  = (const float*)d_in[6];
    const float* proj_w = (const float*)d_in[7];
    const float* proj_b = (const float*)d_in[8];
    const float* ln_g   = (const float*)d_in[9];
    const float* ln_b   = (const float*)d_in[10];
    const float* fc1_w  = (const float*)d_in[11];
    const float* fc1_b  = (const float*)d_in[12];
    const float* fc2_w  = (const float*)d_in[13];
    const float* fc2_b  = (const float*)d_in[14];
    float* out = (float*)d_out;

    __nv_bfloat16 *p_win, *p_qkv, *p_attn, *p_f, *p_hid, *p_wq, *p_wp, *p_w1, *p_w2;
    float *p_xtok, *p_y;
    cudaGetSymbolAddress((void**)&p_win, g_win);
    cudaGetSymbolAddress((void**)&p_qkv, g_qkv);
    cudaGetSymbolAddress((void**)&p_attn, g_attn);
    cudaGetSymbolAddress((void**)&p_f, g_f);
    cudaGetSymbolAddress((void**)&p_hid, g_hid);
    cudaGetSymbolAddress((void**)&p_wq, g_wq);
    cudaGetSymbolAddress((void**)&p_wp, g_wp);
    cudaGetSymbolAddress((void**)&p_w1, g_w1);
    cudaGetSymbolAddress((void**)&p_w2, g_w2);
    cudaGetSymbolAddress((void**)&p_xtok, g_xtok);
    cudaGetSymbolAddress((void**)&p_y, g_y);

    const int GSM = 40960;   // 2-stage double-buffered tiles

    // 0. weight transpose + bf16
    wprep_kernel<<<768, 256>>>(qkv_w, proj_w, fc1_w, fc2_w);

    // 1. BN + window partition (bf16) + raw token copy (fp32)
    bn_window_kernel<<<dim3(896, 4, 4), 256>>>(x, bn_g, bn_b, bn_m, bn_v, p_win, p_xtok);

    // 2. QKV GEMM (HMMA bf16): (200704 x 128) @ (128 x 384)
    mma_gemm<128, 384, 0><<<dim3(3, 1568), 256, GSM>>>(
        p_win, p_wq, qkv_b, p_qkv, nullptr, nullptr, nullptr, nullptr);

    // 3. Windowed attention (HMMA)
    attn_mma_kernel<<<dim3(1024, 4), 128>>>(p_qkv, p_attn);

    // 4. Proj GEMM + window-reverse + residual -> g_y (fp32) + FUSED LayerNorm -> g_f (bf16)
    mma_gemm<128, 128, 1><<<dim3(1, 1568), 256, GSM>>>(
        p_attn, p_wp, proj_b, p_y, p_xtok, ln_g, ln_b, p_f);

    // 5. fc1 GEMM + exact GELU -> bf16 hidden
    mma_gemm<128, 512, 2><<<dim3(4, 1568), 256, GSM>>>(
        p_f, p_w1, fc1_b, p_hid, nullptr, nullptr, nullptr, nullptr);

    // 6. fc2 GEMM + residual + transpose store -> out (B,C,T,H,W)
    mma_gemm<512, 128, 3><<<dim3(1, 1568), 256, GSM>>>(
        p_hid, p_w2, fc2_b, out, p_y, nullptr, nullptr, nullptr);
}

// round 9
// speedup vs baseline: 4.7756x; 1.0228x over previous
#include <cuda_runtime.h>
#include <cuda_bf16.h>
#include <math.h>
#include <stdint.h>

// ---------------- problem constants ----------------
#define Bb   4
#define Cc   128
#define Tt   16
#define Hh   56
#define Ww   56
#define THW  50176      // Tt*Hh*Ww
#define TOK  200704     // Bb*THW
#define NTOK 196        // 4*7*7
#define HID  512
#define NPAD 208        // 13*16
#define SSTR 40         // attn smem row stride in bf16

// ---------------- scratch (device globals) ----------------
__device__ __nv_bfloat16 g_win [(size_t)TOK * Cc];    // BN'd windows (bf16, window order)
__device__ __nv_bfloat16 g_qkv [(size_t)TOK * 384];   // qkv (bf16, window order)
__device__ __nv_bfloat16 g_attn[(size_t)TOK * Cc];    // attention out (bf16, window order)
__device__ __nv_bfloat16 g_f   [(size_t)TOK * Cc];    // LN out (bf16, token order)
__device__ float         g_xtok[(size_t)TOK * Cc];    // raw x (fp32, token order)
__device__ float         g_y   [(size_t)TOK * Cc];    // x + attn residual (fp32, token order)
// transposed bf16 weights [N][K]
__device__ __nv_bfloat16 g_wq[384 * 128];
__device__ __nv_bfloat16 g_wp[128 * 128];
__device__ __nv_bfloat16 g_w1[512 * 128];
__device__ __nv_bfloat16 g_w2[128 * 512];

// ---------------- helpers ----------------
__device__ __forceinline__ uint32_t smem_u32(const void* p) {
    uint32_t a;
    asm("{ .reg .u64 t; cvta.to.shared.u64 t, %1; cvt.u32.u64 %0, t; }" : "=r"(a) : "l"(p));
    return a;
}
__device__ __forceinline__ void ldsm4(uint32_t* r, uint32_t addr) {
    asm volatile("ldmatrix.sync.aligned.m8n8.x4.shared.b16 {%0,%1,%2,%3}, [%4];"
        : "=r"(r[0]), "=r"(r[1]), "=r"(r[2]), "=r"(r[3]) : "r"(addr));
}
__device__ __forceinline__ void ldsm4t(uint32_t* r, uint32_t addr) {
    asm volatile("ldmatrix.sync.aligned.m8n8.x4.trans.shared.b16 {%0,%1,%2,%3}, [%4];"
        : "=r"(r[0]), "=r"(r[1]), "=r"(r[2]), "=r"(r[3]) : "r"(addr));
}
__device__ __forceinline__ void mma_bf16(float* d, const uint32_t* a, uint32_t b0, uint32_t b1) {
    asm volatile(
        "mma.sync.aligned.m16n8k16.row.col.f32.bf16.bf16.f32 "
        "{%0,%1,%2,%3}, {%4,%5,%6,%7}, {%8,%9}, {%0,%1,%2,%3};"
        : "+f"(d[0]), "+f"(d[1]), "+f"(d[2]), "+f"(d[3])
        : "r"(a[0]), "r"(a[1]), "r"(a[2]), "r"(a[3]), "r"(b0), "r"(b1));
}
__device__ __forceinline__ uint32_t pk_bf2(float x, float y) {
    __nv_bfloat162 h = __floats2bfloat162_rn(x, y);
    return *(uint32_t*)&h;
}
__device__ __forceinline__ float gelu_exact(float v) {
    return 0.5f * v * (1.0f + erff(v * 0.7071067811865475f));
}
__device__ __forceinline__ void cpa16(uint32_t dst, const void* src) {
    asm volatile("cp.async.cg.shared.global [%0], [%1], 16;" :: "r"(dst), "l"(src));
}

// ============================================================
// Weight transpose + bf16 convert: W[K][N] -> Wt[N][K] bf16
// ============================================================
__global__ __launch_bounds__(256) void wprep_kernel(
    const float* __restrict__ qkv_w, const float* __restrict__ proj_w,
    const float* __restrict__ fc1_w, const float* __restrict__ fc2_w)
{
    int i = blockIdx.x * 256 + threadIdx.x;
    if (i < 49152) {                       // qkv: 384x128
        int n = i >> 7, k = i & 127;
        g_wq[i] = __float2bfloat16_rn(qkv_w[k * 384 + n]);
    } else if (i < 65536) {                // proj: 128x128
        int j = i - 49152; int n = j >> 7, k = j & 127;
        g_wp[j] = __float2bfloat16_rn(proj_w[k * 128 + n]);
    } else if (i < 131072) {               // fc1: 512x128
        int j = i - 65536; int n = j >> 7, k = j & 127;
        g_w1[j] = __float2bfloat16_rn(fc1_w[k * 512 + n]);
    } else if (i < 196608) {               // fc2: 128x512
        int j = i - 131072; int n = j >> 9, k = j & 511;
        g_w2[j] = __float2bfloat16_rn(fc2_w[k * 128 + n]);
    }
}

// ============================================================
// BN + window partition (bf16) + token-major raw copy (fp32)
// ============================================================
__global__ __launch_bounds__(256) void bn_window_kernel(
    const float* __restrict__ x, const float* __restrict__ gamma,
    const float* __restrict__ beta, const float* __restrict__ mean,
    const float* __restrict__ var, __nv_bfloat16* __restrict__ win,
    float* __restrict__ xtok)
{
    __shared__ float rawS[32][57];
    __shared__ float bnS[32][57];
    const int gx = blockIdx.x;
    const int t = gx / 56, h = gx % 56;
    const int c0 = blockIdx.y * 32;
    const int b = blockIdx.z;
    const int tid = threadIdx.x;

#pragma unroll
    for (int it = 0; it < 7; it++) {
        int idx = tid + it * 256;
        int i = idx / 56, j = idx % 56;
        int c = c0 + i;
        size_t off = ((((size_t)b * Cc + c) * Tt + t) * Hh + h) * Ww + j;
        float v = x[off];
        rawS[i][j] = v;
        float inv = rsqrtf(var[c] + 1e-5f);
        bnS[i][j] = (v - mean[c]) * (inv * gamma[c]) + beta[c];
    }
    __syncthreads();

    const int tblk = t >> 2, wt = t & 3;
    const int hblk = h / 7, wh = h % 7;
#pragma unroll
    for (int it = 0; it < 7; it++) {
        int idx = tid + it * 256;
        int i = idx & 31, j = idx >> 5;
        int wblk = j / 7, ww2 = j % 7;
        int widx = ((b * 4 + tblk) * 8 + hblk) * 8 + wblk;
        int n = (wt * 7 + wh) * 7 + ww2;
        win[((size_t)widx * NTOK + n) * Cc + c0 + i] = __float2bfloat16_rn(bnS[i][j]);
        size_t tok = (size_t)b * THW + ((size_t)t * Hh + h) * Ww + j;
        xtok[tok * Cc + c0 + i] = rawS[i][j];
    }
}

// ============================================================
// bf16 HMMA GEMM, CTA tile 128x128, 8 warps (4Mx2N), warp tile 32x64.
// cp.async 2-stage pipeline, K-chunk 32, double-buffered dynamic smem (40KB).
// EPI 0: bf16 +bias (qkv)
// EPI 1: fp32 +bias+res window->token scatter (proj) + FUSED LayerNorm -> fout bf16
// ============================================================
template<int KTOT, int NOUT, int EPI>
__global__ __launch_bounds__(256) void mma_gemm(
    const __nv_bfloat16* __restrict__ A, const __nv_bfloat16* __restrict__ Bm,
    const float* __restrict__ bias, void* __restrict__ outv,
    const float* __restrict__ res,
    const float* __restrict__ lng, const float* __restrict__ lnb,
    __nv_bfloat16* __restrict__ fout)
{
    extern __shared__ char dsm[];
    const uint32_t sA = smem_u32(dsm);            // [2][128][40] bf16
    const uint32_t sB = sA + 20480;               // [2][128][40] bf16
    const int tid = threadIdx.x;
    const int nb = blockIdx.x * 128;
    const int rb = blockIdx.y * 128;
    const int lane = tid & 31, wid = tid >> 5;
    const int wm = wid >> 1, wn = wid & 1;        // warp grid 4(M) x 2(N)

    float acc[2][8][4];
#pragma unroll
    for (int mt = 0; mt < 2; mt++)
#pragma unroll
        for (int nt = 0; nt < 8; nt++)
#pragma unroll
            for (int j = 0; j < 4; j++) acc[mt][nt][j] = 0.f;

    const int aRow = lane & 15, aKH = lane >> 4;
    const int bRow = ((lane >> 4) << 3) + (lane & 7);
    const int bKH = (lane >> 3) & 1;
    const int ldRow = tid >> 2, ldC = tid & 3;

    auto preload = [&](int ch) {
        const int b = ch & 1, k0 = ch * 32;
#pragma unroll
        for (int p = 0; p < 2; p++) {
            int row = ldRow + p * 64;
            uint32_t off = (uint32_t)(b * 10240 + row * 80 + ldC * 16);
            cpa16(sA + off, A + (size_t)(rb + row) * KTOT + k0 + ldC * 8);
            cpa16(sB + off, Bm + (size_t)(nb + row) * KTOT + k0 + ldC * 8);
        }
        asm volatile("cp.async.commit_group;");
    };

    constexpr int CH = KTOT / 32;
    preload(0);
    for (int ch = 0; ch < CH; ch++) {
        if (ch + 1 < CH) {
            preload(ch + 1);
            asm volatile("cp.async.wait_group 1;");
        } else {
            asm volatile("cp.async.wait_group 0;");
        }
        __syncthreads();
        const uint32_t bA = sA + (ch & 1) * 10240;
        const uint32_t bB = sB + (ch & 1) * 10240;
#pragma unroll
        for (int ks = 0; ks < 2; ks++) {
            const int kk = ks * 16;
            uint32_t a[2][4], b[4][4];
#pragma unroll
            for (int mt = 0; mt < 2; mt++)
                ldsm4(a[mt], bA + (wm * 32 + mt * 16 + aRow) * 80 + (kk + aKH * 8) * 2);
#pragma unroll
            for (int np = 0; np < 4; np++)
                ldsm4(b[np], bB + (wn * 64 + np * 16 + bRow) * 80 + (kk + bKH * 8) * 2);
#pragma unroll
            for (int mt = 0; mt < 2; mt++)
#pragma unroll
                for (int nt = 0; nt < 8; nt++)
                    mma_bf16(acc[mt][nt], a[mt], b[nt >> 1][(nt & 1) * 2],
                             b[nt >> 1][(nt & 1) * 2 + 1]);
        }
        __syncthreads();
    }

    // ---------------- epilogue ----------------
    const int gid = lane >> 2, tig = lane & 3;

    if constexpr (EPI == 0) {
#pragma unroll
        for (int mt = 0; mt < 2; mt++) {
#pragma unroll
            for (int half = 0; half < 2; half++) {
                const int R = rb + wm * 32 + mt * 16 + half * 8 + gid;
                __nv_bfloat16* po = (__nv_bfloat16*)outv + (size_t)R * NOUT;
#pragma unroll
                for (int nt = 0; nt < 8; nt++) {
                    int c = nb + wn * 64 + nt * 8 + tig * 2;
                    float v0 = acc[mt][nt][half * 2]     + bias[c];
                    float v1 = acc[mt][nt][half * 2 + 1] + bias[c + 1];
                    *(__nv_bfloat162*)(po + c) = __floats2bfloat162_rn(v0, v1);
                }
            }
        }
    } else {
        // EPI 1: proj + residual + fused LayerNorm
        size_t toks[2][2];
        float rsum[2][2], rsq[2][2];
#pragma unroll
        for (int mt = 0; mt < 2; mt++) {
#pragma unroll
            for (int half = 0; half < 2; half++) {
                const int R = rb + wm * 32 + mt * 16 + half * 8 + gid;
                unsigned r = (unsigned)R;
                unsigned widx = r / 196u, nl = r - widx * 196u;
                unsigned wblk = widx & 7u, hblk = (widx >> 3) & 7u;
                unsigned tblk = (widx >> 6) & 3u, bbx = widx >> 8;
                unsigned wt = nl / 49u, rem = nl - wt * 49u;
                unsigned wh = rem / 7u, w2 = rem - wh * 7u;
                unsigned th = tblk * 4 + wt, hp = hblk * 7 + wh, wp = wblk * 7 + w2;
                size_t tok = (size_t)bbx * THW + ((size_t)th * Hh + hp) * Ww + wp;
                toks[mt][half] = tok;
                float* po = (float*)outv + tok * Cc;
                const float* pr = res + tok * Cc;
                float s = 0.f, q = 0.f;
#pragma unroll
                for (int nt = 0; nt < 8; nt++) {
                    int c = wn * 64 + nt * 8 + tig * 2;
                    float2 xr = *(const float2*)(pr + c);
                    float y0 = acc[mt][nt][half * 2]     + bias[c]     + xr.x;
                    float y1 = acc[mt][nt][half * 2 + 1] + bias[c + 1] + xr.y;
                    acc[mt][nt][half * 2]     = y0;
                    acc[mt][nt][half * 2 + 1] = y1;
                    float2 o; o.x = y0; o.y = y1;
                    *(float2*)(po + c) = o;
                    s += y0 + y1;
                    q += y0 * y0 + y1 * y1;
                }
                rsum[mt][half] = s; rsq[mt][half] = q;
            }
        }
#pragma unroll
        for (int mt = 0; mt < 2; mt++)
#pragma unroll
            for (int half = 0; half < 2; half++) {
                rsum[mt][half] += __shfl_xor_sync(0xffffffffu, rsum[mt][half], 1);
                rsum[mt][half] += __shfl_xor_sync(0xffffffffu, rsum[mt][half], 2);
                rsq[mt][half]  += __shfl_xor_sync(0xffffffffu, rsq[mt][half], 1);
                rsq[mt][half]  += __shfl_xor_sync(0xffffffffu, rsq[mt][half], 2);
            }
        float2* red = (float2*)dsm;              // [128][2] (reuses GEMM smem)
        __syncthreads();
        if (tig == 0) {
#pragma unroll
            for (int mt = 0; mt < 2; mt++)
#pragma unroll
                for (int half = 0; half < 2; half++) {
                    int r = wm * 32 + mt * 16 + half * 8 + gid;
                    float2 v; v.x = rsum[mt][half]; v.y = rsq[mt][half];
                    red[r * 2 + wn] = v;
                }
        }
        __syncthreads();
#pragma unroll
        for (int mt = 0; mt < 2; mt++) {
#pragma unroll
            for (int half = 0; half < 2; half++) {
                int r = wm * 32 + mt * 16 + half * 8 + gid;
                float2 p0 = red[r * 2], p1 = red[r * 2 + 1];
                float mu = (p0.x + p1.x) * (1.f / 128.f);
                float var = (p0.y + p1.y) * (1.f / 128.f) - mu * mu;
                float inv = rsqrtf(var + 1e-5f);
                __nv_bfloat16* pf = fout + toks[mt][half] * Cc;
#pragma unroll
                for (int nt = 0; nt < 8; nt++) {
                    int c = wn * 64 + nt * 8 + tig * 2;
                    float2 gg = *(const float2*)(lng + c);
                    float2 bb = *(const float2*)(lnb + c);
                    float f0 = (acc[mt][nt][half * 2]     - mu) * inv * gg.x + bb.x;
                    float f1 = (acc[mt][nt][half * 2 + 1] - mu) * inv * gg.y + bb.y;
                    *(__nv_bfloat162*)(pf + c) = __floats2bfloat162_rn(f0, f1);
                }
            }
        }
    }
}

// ============================================================
// FUSED MLP: out = fc2(gelu(fc1(f))) + y, transposed store to (B,C,THW).
// One CTA per 128 rows. f tile + weight chunk + hidden tile in smem
// (stride 136 bf16 = 272B rows -> conflict-free ldmatrix & stores).
// Loop over 4 hidden chunks of 128: phase1 h=gelu(f@w1c+b1), phase2 o+=h@w2c.
// ============================================================
__global__ __launch_bounds__(256, 1) void mlp_kernel(
    const __nv_bfloat16* __restrict__ f, const __nv_bfloat16* __restrict__ w1,
    const __nv_bfloat16* __restrict__ w2, const float* __restrict__ b1,
    const float* __restrict__ b2, const float* __restrict__ res,
    float* __restrict__ out)
{
    extern __shared__ char dsm[];
    const uint32_t sF = smem_u32(dsm);            // [128][136] bf16
    const uint32_t sW = sF + 34816;               // [128][136] bf16
    const uint32_t sH = sW + 34816;               // [128][136] bf16
    const int tid = threadIdx.x;
    const int rb = blockIdx.x * 128;
    const int lane = tid & 31, wid = tid >> 5;
    const int wm = wid >> 1, wn = wid & 1;        // warp grid 4(M) x 2(N)

    const int aRow = lane & 15, aKH = lane >> 4;
    const int bRow = ((lane >> 4) << 3) + (lane & 7);
    const int bKH = (lane >> 3) & 1;
    const int gid = lane >> 2, tig = lane & 3;

    // stage f tile (128 x 128 bf16)
#pragma unroll
    for (int it = 0; it < 8; it++) {
        int idx = tid + it * 256;
        int row = idx >> 4, c8 = idx & 15;
        cpa16(sF + row * 272 + c8 * 16, f + (size_t)(rb + row) * Cc + c8 * 8);
    }
    asm volatile("cp.async.commit_group;");

    float oacc[2][8][4];
#pragma unroll
    for (int mt = 0; mt < 2; mt++)
#pragma unroll
        for (int nt = 0; nt < 8; nt++)
#pragma unroll
            for (int j = 0; j < 4; j++) oacc[mt][nt][j] = 0.f;

    for (int nc = 0; nc < 4; nc++) {
        // ---- load w1 chunk [128 n][128 k] ----
        __syncthreads();          // sW free (prev phase2 done), sH free
#pragma unroll
        for (int it = 0; it < 8; it++) {
            int idx = tid + it * 256;
            int row = idx >> 4, c8 = idx & 15;
            cpa16(sW + row * 272 + c8 * 16,
                  w1 + (size_t)(nc * 128 + row) * Cc + c8 * 8);
        }
        asm volatile("cp.async.commit_group;");
        asm volatile("cp.async.wait_group 0;");
        __syncthreads();

        // ---- phase 1: hacc = f @ w1c ----
        float hacc[2][8][4];
#pragma unroll
        for (int mt = 0; mt < 2; mt++)
#pragma unroll
            for (int nt = 0; nt < 8; nt++)
#pragma unroll
                for (int j = 0; j < 4; j++) hacc[mt][nt][j] = 0.f;
#pragma unroll
        for (int ks = 0; ks < 8; ks++) {
            const int kk = ks * 16;
            uint32_t a[2][4], b[4][4];
#pragma unroll
            for (int mt = 0; mt < 2; mt++)
                ldsm4(a[mt], sF + (wm * 32 + mt * 16 + aRow) * 272 + (kk + aKH * 8) * 2);
#pragma unroll
            for (int np = 0; np < 4; np++)
                ldsm4(b[np], sW + (wn * 64 + np * 16 + bRow) * 272 + (kk + bKH * 8) * 2);
#pragma unroll
            for (int mt = 0; mt < 2; mt++)
#pragma unroll
                for (int nt = 0; nt < 8; nt++)
                    mma_bf16(hacc[mt][nt], a[mt], b[nt >> 1][(nt & 1) * 2],
                             b[nt >> 1][(nt & 1) * 2 + 1]);
        }

        // ---- gelu + store h tile to smem ----
#pragma unroll
        for (int mt = 0; mt < 2; mt++) {
#pragma unroll
            for (int half = 0; half < 2; half++) {
                int row = wm * 32 + mt * 16 + half * 8 + gid;
#pragma unroll
                for (int nt = 0; nt < 8; nt++) {
                    int c = wn * 64 + nt * 8 + tig * 2;
                    float v0 = gelu_exact(hacc[mt][nt][half * 2]     + b1[nc * 128 + c]);
                    float v1 = gelu_exact(hacc[mt][nt][half * 2 + 1] + b1[nc * 128 + c + 1]);
                    uint32_t pk = pk_bf2(v0, v1);
                    asm volatile("st.shared.b32 [%0], %1;"
                                 :: "r"(sH + row * 272 + c * 2), "r"(pk));
                }
            }
        }
        __syncthreads();          // h complete; sW free for w2

        // ---- load w2 chunk [128 n][k = nc*128..+128] ----
#pragma unroll
        for (int it = 0; it < 8; it++) {
            int idx = tid + it * 256;
            int row = idx >> 4, c8 = idx & 15;
            cpa16(sW + row * 272 + c8 * 16,
                  w2 + (size_t)row * HID + nc * 128 + c8 * 8);
        }
        asm volatile("cp.async.commit_group;");
        asm volatile("cp.async.wait_group 0;");
        __syncthreads();

        // ---- phase 2: oacc += h @ w2c ----
#pragma unroll
        for (int ks = 0; ks < 8; ks++) {
            const int kk = ks * 16;
            uint32_t a[2][4], b[4][4];
#pragma unroll
            for (int mt = 0; mt < 2; mt++)
                ldsm4(a[mt], sH + (wm * 32 + mt * 16 + aRow) * 272 + (kk + aKH * 8) * 2);
#pragma unroll
            for (int np = 0; np < 4; np++)
                ldsm4(b[np], sW + (wn * 64 + np * 16 + bRow) * 272 + (kk + bKH * 8) * 2);
#pragma unroll
            for (int mt = 0; mt < 2; mt++)
#pragma unroll
                for (int nt = 0; nt < 8; nt++)
                    mma_bf16(oacc[mt][nt], a[mt], b[nt >> 1][(nt & 1) * 2],
                             b[nt >> 1][(nt & 1) * 2 + 1]);
        }
    }

    // ---- final epilogue: +bias +residual, transpose store (B,C,THW) ----
#pragma unroll
    for (int mt = 0; mt < 2; mt++) {
#pragma unroll
        for (int half = 0; half < 2; half++) {
            const int R = rb + wm * 32 + mt * 16 + half * 8 + gid;
            unsigned bq = (unsigned)R / (unsigned)THW;
            unsigned thw = (unsigned)R - bq * (unsigned)THW;
            const float* pr = res + (size_t)R * Cc;
#pragma unroll
            for (int nt = 0; nt < 8; nt++) {
                int c = wn * 64 + nt * 8 + tig * 2;
                float2 xr = *(const float2*)(pr + c);
                out[(size_t)(bq * Cc + c) * THW + thw] =
                    oacc[mt][nt][half * 2] + b2[c] + xr.x;
                out[(size_t)(bq * Cc + c + 1) * THW + thw] =
                    oacc[mt][nt][half * 2 + 1] + b2[c + 1] + xr.y;
            }
        }
    }
}

// ============================================================
// HMMA attention: one CTA per (window, head), 4 warps.
// ============================================================
__global__ __launch_bounds__(128) void attn_mma_kernel(
    const __nv_bfloat16* __restrict__ qkv, __nv_bfloat16* __restrict__ outp)
{
    __shared__ __nv_bfloat16 Ks[NPAD * SSTR];
    __shared__ __nv_bfloat16 Vs[NPAD * SSTR];
    const int widx = blockIdx.x, hh = blockIdx.y;
    const size_t base = (size_t)widx * NTOK * 384 + hh * 32;
    const int tid = threadIdx.x;
    const int lane = tid & 31, wid = tid >> 5;

    for (int idx = tid; idx < 3136; idx += 128) {
        int row = idx >> 4, u = idx & 15;
        const uint32_t* src = (const uint32_t*)(qkv + base + (size_t)row * 384);
        *(uint32_t*)(Ks + row * SSTR + u * 2) = src[64 + u];
        *(uint32_t*)(Vs + row * SSTR + u * 2) = src[128 + u];
    }
    for (int idx = tid; idx < 12 * 16; idx += 128) {
        int row = 196 + (idx >> 4), u = idx & 15;
        *(uint32_t*)(Ks + row * SSTR + u * 2) = 0;
        *(uint32_t*)(Vs + row * SSTR + u * 2) = 0;
    }
    __syncthreads();

    const int g = lane >> 2, tig = lane & 3;
    const int bRow = ((lane >> 4) << 3) + (lane & 7), bKH = (lane >> 3) & 1;
    const int vKrow = (lane & 7) + ((lane >> 3) & 1) * 8;
    const int vNh = ((lane >> 4) & 1) * 8;
    const float sc = 0.17677669529663688f;    // 1/sqrt(32)

    for (int mt = wid; mt < 13; mt += 4) {
        const int m0 = mt * 16;
        int r0 = m0 + g;     if (r0 > 195) r0 = 195;
        int r1 = m0 + g + 8; if (r1 > 195) r1 = 195;
        const __nv_bfloat16* q0 = qkv + base + (size_t)r0 * 384 + tig * 2;
        const __nv_bfloat16* q1 = qkv + base + (size_t)r1 * 384 + tig * 2;
        uint32_t qa[2][4];
        qa[0][0] = *(const uint32_t*)(q0);
        qa[0][1] = *(const uint32_t*)(q1);
        qa[0][2] = *(const uint32_t*)(q0 + 8);
        qa[0][3] = *(const uint32_t*)(q1 + 8);
        qa[1][0] = *(const uint32_t*)(q0 + 16);
        qa[1][1] = *(const uint32_t*)(q1 + 16);
        qa[1][2] = *(const uint32_t*)(q0 + 24);
        qa[1][3] = *(const uint32_t*)(q1 + 24);

        float oacc[4][4];
#pragma unroll
        for (int nt = 0; nt < 4; nt++)
#pragma unroll
            for (int j = 0; j < 4; j++) oacc[nt][j] = 0.f;
        float rs0 = 0.f, rs1 = 0.f;

        for (int ks = 0; ks < 13; ks++) {
            uint32_t kb0[4], kb1[4];
            ldsm4(kb0, smem_u32(Ks + (ks * 16 + bRow) * SSTR + bKH * 8));
            ldsm4(kb1, smem_u32(Ks + (ks * 16 + bRow) * SSTR + 16 + bKH * 8));

            float s0[4] = {0.f, 0.f, 0.f, 0.f}, s1[4] = {0.f, 0.f, 0.f, 0.f};
            mma_bf16(s0, qa[0], kb0[0], kb0[1]);
            mma_bf16(s0, qa[1], kb1[0], kb1[1]);
            mma_bf16(s1, qa[0], kb0[2], kb0[3]);
            mma_bf16(s1, qa[1], kb1[2], kb1[3]);

            float e0[4], e1[4];
#pragma unroll
            for (int j = 0; j < 4; j++) {
                e0[j] = __expf(s0[j] * sc);
                e1[j] = __expf(s1[j] * sc);
            }
            if (ks == 12) {
#pragma unroll
                for (int j = 0; j < 4; j++) e1[j] = 0.f;
                if (tig >= 2) {
#pragma unroll
                    for (int j = 0; j < 4; j++) e0[j] = 0.f;
                }
            }
            rs0 += e0[0] + e0[1] + e1[0] + e1[1];
            rs1 += e0[2] + e0[3] + e1[2] + e1[3];

            uint32_t pa[4];
            pa[0] = pk_bf2(e0[0], e0[1]);
            pa[1] = pk_bf2(e0[2], e0[3]);
            pa[2] = pk_bf2(e1[0], e1[1]);
            pa[3] = pk_bf2(e1[2], e1[3]);

            uint32_t vb0[4], vb1[4];
            uint32_t va = smem_u32(Vs + (ks * 16 + vKrow) * SSTR + vNh);
            ldsm4t(vb0, va);
            ldsm4t(vb1, va + 32);
            mma_bf16(oacc[0], pa, vb0[0], vb0[1]);
            mma_bf16(oacc[1], pa, vb0[2], vb0[3]);
            mma_bf16(oacc[2], pa, vb1[0], vb1[1]);
            mma_bf16(oacc[3], pa, vb1[2], vb1[3]);
        }

        rs0 += __shfl_xor_sync(0xffffffffu, rs0, 1);
        rs0 += __shfl_xor_sync(0xffffffffu, rs0, 2);
        rs1 += __shfl_xor_sync(0xffffffffu, rs1, 1);
        rs1 += __shfl_xor_sync(0xffffffffu, rs1, 2);
        float i0 = 1.f / rs0, i1 = 1.f / rs1;

        const int w0 = m0 + g, w1 = m0 + g + 8;
        if (w0 < NTOK) {
            __nv_bfloat16* p = outp + ((size_t)widx * NTOK + w0) * Cc + hh * 32 + tig * 2;
#pragma unroll
            for (int nt = 0; nt < 4; nt++)
                *(__nv_bfloat162*)(p + nt * 8) =
                    __floats2bfloat162_rn(oacc[nt][0] * i0, oacc[nt][1] * i0);
        }
        if (w1 < NTOK) {
            __nv_bfloat16* p = outp + ((size_t)widx * NTOK + w1) * Cc + hh * 32 + tig * 2;
#pragma unroll
            for (int nt = 0; nt < 4; nt++)
                *(__nv_bfloat162*)(p + nt * 8) =
                    __floats2bfloat162_rn(oacc[nt][2] * i1, oacc[nt][3] * i1);
        }
    }
}

// ============================================================
// Launch
// ============================================================
extern "C" void kernel_launch(void* const* d_in, const int* in_sizes, int n_in,
                              void* d_out, int out_size)
{
    const float* x      = (const float*)d_in[0];
    const float* bn_g   = (const float*)d_in[1];
    const float* bn_b   = (const float*)d_in[2];
    const float* bn_m   = (const float*)d_in[3];
    const float* bn_v   = (const float*)d_in[4];
    const float* qkv_w  = (const float*)d_in[5];
    const float* qkv_b  = (const float*)d_in[6];
    const float* proj_w = (const float*)d_in[7];
    const float* proj_b = (const float*)d_in[8];
    const float* ln_g   = (const float*)d_in[9];
    const float* ln_b   = (const float*)d_in[10];
    const float* fc1_w  = (const float*)d_in[11];
    const float* fc1_b  = (const float*)d_in[12];
    const float* fc2_w  = (const float*)d_in[13];
    const float* fc2_b  = (const float*)d_in[14];
    float* out = (float*)d_out;

    __nv_bfloat16 *p_win, *p_qkv, *p_attn, *p_f, *p_wq, *p_wp, *p_w1, *p_w2;
    float *p_xtok, *p_y;
    cudaGetSymbolAddress((void**)&p_win, g_win);
    cudaGetSymbolAddress((void**)&p_qkv, g_qkv);
    cudaGetSymbolAddress((void**)&p_attn, g_attn);
    cudaGetSymbolAddress((void**)&p_f, g_f);
    cudaGetSymbolAddress((void**)&p_wq, g_wq);
    cudaGetSymbolAddress((void**)&p_wp, g_wp);
    cudaGetSymbolAddress((void**)&p_w1, g_w1);
    cudaGetSymbolAddress((void**)&p_w2, g_w2);
    cudaGetSymbolAddress((void**)&p_xtok, g_xtok);
    cudaGetSymbolAddress((void**)&p_y, g_y);

    const int GSM = 40960;       // gemm: double-buffered tiles
    const int MSM = 104448;      // mlp: f + w + h tiles
    cudaFuncSetAttribute(mlp_kernel, cudaFuncAttributeMaxDynamicSharedMemorySize, MSM);

    // 0. weight transpose + bf16
    wprep_kernel<<<768, 256>>>(qkv_w, proj_w, fc1_w, fc2_w);

    // 1. BN + window partition (bf16) + raw token copy (fp32)
    bn_window_kernel<<<dim3(896, 4, 4), 256>>>(x, bn_g, bn_b, bn_m, bn_v, p_win, p_xtok);

    // 2. QKV GEMM (HMMA bf16): (200704 x 128) @ (128 x 384)
    mma_gemm<128, 384, 0><<<dim3(3, 1568), 256, GSM>>>(
        p_win, p_wq, qkv_b, p_qkv, nullptr, nullptr, nullptr, nullptr);

    // 3. Windowed attention (HMMA)
    attn_mma_kernel<<<dim3(1024, 4), 128>>>(p_qkv, p_attn);

    // 4. Proj GEMM + window-reverse + residual -> g_y (fp32) + FUSED LayerNorm -> g_f (bf16)
    mma_gemm<128, 128, 1><<<dim3(1, 1568), 256, GSM>>>(
        p_attn, p_wp, proj_b, p_y, p_xtok, ln_g, ln_b, p_f);

    // 5. FUSED MLP (fc1 + gelu + fc2 + residual + transpose store)
    mlp_kernel<<<1568, 256, MSM>>>(p_f, p_w1, p_w2, fc1_b, fc2_b, p_y, out);
}